// round 11
// baseline (speedup 1.0000x reference)
#include <cuda_runtime.h>
#include <cuda_bf16.h>
#include <math.h>
#include <stdint.h>

#define B 8
#define OUTD 592002
#define WMTOT 589824
typedef __nv_bfloat16 bf;

// ---------------- device globals ----------------
__device__ float g_w[(size_t)B * OUTD];
__device__ float g_h2[B * 32];
__device__ __align__(16) float2 g_wp0[(size_t)B * 640];
__device__ __align__(16) bf g_wmc[(size_t)B * WMTOT * 2];   // interleaved hi/lo mma weights
__device__ __align__(16) bf g_Ah[(size_t)B * 128 * 65536];
__device__ __align__(16) bf g_Al[(size_t)B * 128 * 65536];
__device__ __align__(16) bf g_Bh[(size_t)B * 128 * 65536];
__device__ __align__(16) bf g_Bl[(size_t)B * 128 * 65536];
__device__ __align__(16) bf g_S1h[(size_t)B * 64 * 65536];
__device__ __align__(16) bf g_S1l[(size_t)B * 64 * 65536];
__device__ __align__(16) bf g_S2h[(size_t)B * 64 * 16384];
__device__ __align__(16) bf g_S2l[(size_t)B * 64 * 16384];
__device__ __align__(16) bf g_S3h[(size_t)B * 64 * 4096];
__device__ __align__(16) bf g_S3l[(size_t)B * 64 * 4096];

__constant__ int cWM[13] = {0, 36864, 73728, 110592, 147456, 184320, 221184, 258048,
                            331776, 368640, 442368, 479232, 552960};
__constant__ int cK2[13] = {1152, 38016, 74880, 111744, 148608, 185472, 222336, 259200,
                            332928, 369792, 443520, 480384, 554112};
__constant__ int cCIN2[13] = {64, 64, 64, 64, 64, 64, 64, 128, 64, 128, 64, 128, 64};

// ---------------- helpers ----------------
__device__ __forceinline__ void fma2(unsigned long long& a, unsigned long long x, unsigned long long w)
{ asm("fma.rn.f32x2 %0, %1, %2, %0;" : "+l"(a) : "l"(x), "l"(w)); }
__device__ __forceinline__ unsigned long long pack2b(float a)
{ unsigned long long r; asm("mov.b64 %0, {%1, %1};" : "=l"(r) : "f"(a)); return r; }
__device__ __forceinline__ float2 unpack2(unsigned long long v)
{ float2 r; asm("mov.b64 {%0, %1}, %2;" : "=f"(r.x), "=f"(r.y) : "l"(v)); return r; }
__device__ __forceinline__ void cp16(uint32_t d, const void* s)
{ asm volatile("cp.async.cg.shared.global [%0], [%1], 16;" :: "r"(d), "l"(s) : "memory"); }
__device__ __forceinline__ void cp16z(uint32_t d, const void* s, int sz)
{ asm volatile("cp.async.cg.shared.global [%0], [%1], 16, %2;" :: "r"(d), "l"(s), "r"(sz) : "memory"); }
__device__ __forceinline__ void cp_commit()
{ asm volatile("cp.async.commit_group;" ::: "memory"); }
__device__ __forceinline__ void cp_wait1()
{ asm volatile("cp.async.wait_group 1;" ::: "memory"); }
__device__ __forceinline__ void cp_wait0()
{ asm volatile("cp.async.wait_group 0;" ::: "memory"); }
__device__ __forceinline__ float joinv(bf h, bf l)
{ return __bfloat162float(h) + __bfloat162float(l); }
__device__ __forceinline__ uint32_t splitp(float v0, float v1, uint32_t& lo)
{
    bf h0 = __float2bfloat16(v0), h1 = __float2bfloat16(v1);
    bf l0 = __float2bfloat16(v0 - __bfloat162float(h0));
    bf l1 = __float2bfloat16(v1 - __bfloat162float(h1));
    lo = (uint32_t)__bfloat16_as_ushort(l0) | ((uint32_t)__bfloat16_as_ushort(l1) << 16);
    return (uint32_t)__bfloat16_as_ushort(h0) | ((uint32_t)__bfloat16_as_ushort(h1) << 16);
}
__device__ __forceinline__ void ldsm4(uint32_t* r, uint32_t a)
{
    asm volatile("ldmatrix.sync.aligned.m8n8.x4.shared.b16 {%0,%1,%2,%3}, [%4];"
                 : "=r"(r[0]), "=r"(r[1]), "=r"(r[2]), "=r"(r[3]) : "r"(a));
}
__device__ __forceinline__ void lds128(uint32_t* v, uint32_t a)
{
    asm volatile("ld.shared.v4.b32 {%0,%1,%2,%3}, [%4];"
                 : "=r"(v[0]), "=r"(v[1]), "=r"(v[2]), "=r"(v[3]) : "r"(a));
}
__device__ __forceinline__ void mma16816(float* d, const uint32_t* a, const uint32_t* bq)
{
    asm volatile("mma.sync.aligned.m16n8k16.row.col.f32.bf16.bf16.f32 "
        "{%0,%1,%2,%3}, {%4,%5,%6,%7}, {%8,%9}, {%0,%1,%2,%3};"
        : "+f"(d[0]), "+f"(d[1]), "+f"(d[2]), "+f"(d[3])
        : "r"(a[0]), "r"(a[1]), "r"(a[2]), "r"(a[3]), "r"(bq[0]), "r"(bq[1]));
}

// ---------------- hypernet ----------------
__global__ void hyper1_kernel(const float* __restrict__ hp, const float* __restrict__ W1,
                              const float* __restrict__ b1, const float* __restrict__ W2,
                              const float* __restrict__ b2, float* __restrict__ l1)
{
    __shared__ float h1[B][32];
    int b = threadIdx.x >> 5, i = threadIdx.x & 31;
    if (threadIdx.x < B) l1[threadIdx.x] = 0.f;
    h1[b][i] = hp[b] * W1[i] + b1[i];
    __syncthreads();
    float a = b2[i];
#pragma unroll
    for (int k = 0; k < 32; k++) a += h1[b][k] * W2[i * 32 + k];
    g_h2[b * 32 + i] = a;
}

__global__ void weightgen_kernel(const float* __restrict__ Wo, const float* __restrict__ bo,
                                 float* __restrict__ l1out)
{
    __shared__ float sh2[B * 32];
    __shared__ float wsum[8][B];
    int tid = threadIdx.x;
    sh2[tid] = g_h2[tid];
    __syncthreads();
    int j = blockIdx.x * 256 + tid;
    float s[B];
#pragma unroll
    for (int b = 0; b < B; b++) s[b] = 0.f;
    if (j < OUTD) {
        float wr[32];
        const float* row = Wo + (size_t)j * 32;
#pragma unroll
        for (int i = 0; i < 32; i++) wr[i] = row[i];
        float bj = bo[j];
#pragma unroll
        for (int b = 0; b < B; b++) {
            float a = bj;
#pragma unroll
            for (int i = 0; i < 32; i++) a += wr[i] * sh2[b * 32 + i];
            float w = tanhf(a);
            g_w[(size_t)b * OUTD + j] = w;
            s[b] = fabsf(w);
        }
    }
    int warp = tid >> 5, lane = tid & 31;
#pragma unroll
    for (int b = 0; b < B; b++) {
        float v = s[b];
        for (int o = 16; o > 0; o >>= 1) v += __shfl_xor_sync(0xFFFFFFFFu, v, o);
        if (lane == 0) wsum[warp][b] = v;
    }
    __syncthreads();
    if (tid < B) {
        float a = 0.f;
#pragma unroll
        for (int w = 0; w < 8; w++) a += wsum[w][tid];
        atomicAdd(&l1out[tid], a);
    }
}

// ---------------- repack layer0 (fp32 pairs) ----------------
__global__ void repack0_kernel()
{
    int e = blockIdx.x * 256 + threadIdx.x;
    if (e >= B * 576) return;
    int b = e / 576, q = e - b * 576;
    int c = q / 288, t = q - c * 288, ocp = t / 9, k = t - ocp * 9;
    const float* wb = g_w + (size_t)b * OUTD;
    g_wp0[(size_t)b * 640 + (c * 32 + ocp) * 10 + k] =
        make_float2(wb[((2 * ocp) * 2 + c) * 9 + k], wb[((2 * ocp + 1) * 2 + c) * 9 + k]);
}

// ---------------- repack layers 1..13: interleaved hi/lo mma-B fragments --------
// chunk g: per lane-quad 16B = [hi(e0..3) | lo(e0..3)]
__global__ void repack_mm_kernel()
{
    int e = blockIdx.x * 256 + threadIdx.x;
    if (e >= B * WMTOT) return;
    int b = e / WMTOT, r = e - b * WMTOT;
    int l = 0;
#pragma unroll
    for (int i = 1; i < 13; i++)
        if (r >= cWM[i]) l = i;
    int rp = r - cWM[l];
    int cin = cCIN2[l], cblk = cin >> 6;
    int g = rp >> 12, idx = rp & 4095;
    int kk = g / cblk, cb = g - kk * cblk;
    int h = idx & 1, j2 = (idx >> 1) & 1, lane = (idx >> 2) & 31;
    int t = (idx >> 7) & 7, s = idx >> 10;
    int oc = t * 8 + (lane >> 2);
    int c = cb * 64 + s * 16 + (lane & 3) * 2 + j2 * 8 + h;
    float w = g_w[(size_t)b * OUTD + cK2[l] + ((oc * cin + c) * 9 + kk)];
    bf hh = __float2bfloat16(w);
    bf ll = __float2bfloat16(w - __bfloat162float(hh));
    size_t dst = (size_t)b * WMTOT * 2 + (size_t)cWM[l] * 2
               + (size_t)g * 8192 + (size_t)(idx >> 2) * 8 + (j2 * 2 + h);
    g_wmc[dst] = hh;
    g_wmc[dst + 4] = ll;
}

// ---------------- layer 0: CIN=2 fp32 conv, NHWC bf16 hi/lo out ----------------
__global__ __launch_bounds__(256) void conv0_kernel(
    const float* __restrict__ zf, bf* __restrict__ oh, bf* __restrict__ ol,
    const float* __restrict__ wbuf)
{
    __shared__ float sIn[2 * 1156];
    __shared__ float2 sW[2 * 72];
    int b = blockIdx.z, ocg = blockIdx.y;
    int ty0 = (blockIdx.x >> 3) << 5, tx0 = (blockIdx.x & 7) << 5;
    int tid = threadIdx.x, tx = tid & 15, ty = tid >> 4;
    const float* inb = zf + (size_t)b * 131072;
    const float2* wpb = g_wp0 + (size_t)b * 640;

    for (int idx = tid; idx < 2 * 1156; idx += 256) {
        int cs = idx / 1156, rem = idx - cs * 1156;
        int r = rem / 34, cc = rem - r * 34;
        int gy = ty0 - 1 + r, gx = tx0 - 1 + cc;
        float v = 0.f;
        if ((unsigned)gy < 256u && (unsigned)gx < 256u)
            v = inb[(((size_t)gy << 8) + gx) * 2 + cs];
        sIn[idx] = v;
    }
    for (int idx = tid; idx < 144; idx += 256) {
        int cs = idx / 72, rem = idx - cs * 72, ocp = rem / 9, k = rem - ocp * 9;
        sW[idx] = wpb[(cs * 32 + ocg * 8 + ocp) * 10 + k];
    }
    __syncthreads();

    unsigned long long acc[8][4];
#pragma unroll
    for (int i = 0; i < 8; i++)
#pragma unroll
        for (int p = 0; p < 4; p++) acc[i][p] = 0ull;
#pragma unroll
    for (int cs = 0; cs < 2; cs++) {
        float xi[16];
#pragma unroll
        for (int r = 0; r < 4; r++)
#pragma unroll
            for (int cc = 0; cc < 4; cc++)
                xi[r * 4 + cc] = sIn[cs * 1156 + (2 * ty + r) * 34 + 2 * tx + cc];
#pragma unroll
        for (int ky = 0; ky < 3; ky++)
#pragma unroll
            for (int kx = 0; kx < 3; kx++) {
                unsigned long long xx[4];
#pragma unroll
                for (int py = 0; py < 2; py++)
#pragma unroll
                    for (int px = 0; px < 2; px++)
                        xx[py * 2 + px] = pack2b(xi[(py + ky) * 4 + (px + kx)]);
#pragma unroll
                for (int o = 0; o < 8; o++) {
                    unsigned long long w =
                        *reinterpret_cast<const unsigned long long*>(&sW[cs * 72 + o * 9 + ky * 3 + kx]);
#pragma unroll
                    for (int p = 0; p < 4; p++) fma2(acc[o][p], xx[p], w);
                }
            }
    }
    const float* wb = wbuf + (size_t)b * OUTD;
#pragma unroll
    for (int o = 0; o < 8; o++) {
        int oc = (ocg * 8 + o) * 2;
        float b0 = wb[591104 + oc], b1 = wb[591104 + oc + 1];
#pragma unroll
        for (int py = 0; py < 2; py++)
#pragma unroll
            for (int px = 0; px < 2; px++) {
                float2 v = unpack2(acc[o][py * 2 + px]);
                float v0 = fmaxf(v.x + b0, 0.f), v1 = fmaxf(v.y + b1, 0.f);
                uint32_t lo, hi = splitp(v0, v1, lo);
                int p = (ty0 + 2 * ty + py) * 256 + tx0 + 2 * tx + px;
                size_t off = ((size_t)b * 65536 + p) * 64 + oc;
                *(uint32_t*)(oh + off) = hi;
                *(uint32_t*)(ol + off) = lo;
            }
    }
}

// ---------------- mma.sync conv layer v2 ----------------
// TM=256: 512 thr, 16 warps = 4 px-tiles(64px) x 4 oc-tiles(16oc).
// TM=128: 256 thr,  8 warps = 4 px-tiles(32px) x 2 oc-tiles(32oc).
// Buffer: AH (TM*128) | AL (TM*128) | Bc 16K(interleaved hi/lo).  Double-buffered.
template<int CIN, int TM>
__global__ __launch_bounds__((TM == 256 ? 512 : 256), (TM == 256 ? 1 : 2)) void convmm_kernel(
    const bf* __restrict__ inh, const bf* __restrict__ inl,
    bf* __restrict__ outh, bf* __restrict__ outl,
    const float* __restrict__ wbuf, int wmoff, int boff, int H, int lgH)
{
    constexpr int CBLK = CIN / 64;
    constexpr int G = 9 * CBLK;
    constexpr int THREADS = (TM == 256) ? 512 : 256;
    constexpr int MT = (TM == 256) ? 4 : 2;   // m16 tiles per warp
    constexpr int NT = (TM == 256) ? 2 : 4;   // n8 tiles per warp
    constexpr int ABYTES = TM * 128;
    constexpr int BUF = 2 * ABYTES + 16384;

    extern __shared__ __align__(128) char smem[];
    __shared__ float sbias[64];
    const int tid = threadIdx.x;
    const int b = blockIdx.z;
    const int p0 = blockIdx.x * TM;
    const int HH = H * H;
    uint32_t sb0 = (uint32_t)__cvta_generic_to_shared(smem);

    if (tid < 64) sbias[tid] = wbuf[(size_t)b * OUTD + boff + tid];

    const bf* ibh = inh + (size_t)b * HH * CIN;
    const bf* ibl = inl + (size_t)b * HH * CIN;
    const char* wcb = (const char*)(g_wmc + (size_t)b * WMTOT * 2 + (size_t)wmoff * 2);

    const int ar = tid >> 1, aj0 = (tid & 1) * 4;
    const int py = p0 + ar;
    const int ay = py >> lgH, ax = py & (H - 1);

    auto stage = [&](int g, int buf) {
        const uint32_t AH = sb0 + buf * BUF, AL = AH + ABYTES, BB = AL + ABYTES;
        const int kk = g / CBLK, cb = g - kk * CBLK;
        const int dy = kk / 3 - 1, dx = kk - (kk / 3) * 3 - 1;
        int gy = ay + dy, gx = ax + dx;
        bool ok = ((unsigned)gy < (unsigned)H) && ((unsigned)gx < (unsigned)H);
        size_t q = ok ? ((size_t)(gy * H + gx) * CIN + cb * 64) : 0;
        const char* sh = (const char*)(ibh + q);
        const char* sl = (const char*)(ibl + q);
        int sz = ok ? 16 : 0;
        uint32_t ro = (uint32_t)ar * 128u, sw = (uint32_t)((ar & 7) << 4);
#pragma unroll
        for (int j = aj0; j < aj0 + 4; j++) {
            uint32_t o = ro + (((uint32_t)j * 16u) ^ sw);
            cp16z(AH + o, sh + j * 16, sz);
            cp16z(AL + o, sl + j * 16, sz);
        }
        const char* wg = wcb + (size_t)g * 16384;
#pragma unroll
        for (int j = 0; j < 16384 / (16 * THREADS); j++) {
            uint32_t o = (uint32_t)(tid + j * THREADS) * 16u;
            cp16(BB + o, wg + o);
        }
    };

    const int lane = tid & 31, w = tid >> 5;
    const int wm = w & 3, wn = w >> 2;
    const int g4 = lane >> 3, li = lane & 7;

    float acc[MT][NT][4];
#pragma unroll
    for (int m = 0; m < MT; m++)
#pragma unroll
        for (int n = 0; n < NT; n++)
#pragma unroll
            for (int i = 0; i < 4; i++) acc[m][n][i] = 0.f;

    stage(0, 0);
    cp_commit();

    for (int g = 0; g < G; g++) {
        if (g + 1 < G) { stage(g + 1, (g + 1) & 1); cp_commit(); cp_wait1(); }
        else           { cp_wait0(); }
        __syncthreads();

        const uint32_t AH = sb0 + (g & 1) * BUF, AL = AH + ABYTES, BB = AL + ABYTES;

#pragma unroll
        for (int s = 0; s < 4; s++) {
            uint32_t a_h[MT][4], a_l[MT][4];
#pragma unroll
            for (int m = 0; m < MT; m++) {
                uint32_t row = (uint32_t)(wm * (MT * 16) + m * 16 + li + (g4 & 1) * 8);
                uint32_t kb = (uint32_t)(s * 32 + (g4 >> 1) * 16);
                uint32_t off = row * 128 + (kb ^ ((row & 7) << 4));
                ldsm4(a_h[m], AH + off);
                ldsm4(a_l[m], AL + off);
            }
            uint32_t bq[NT][4];
#pragma unroll
            for (int n = 0; n < NT; n++) {
                uint32_t nt = (uint32_t)(wn * NT + n);
                lds128(bq[n], BB + ((uint32_t)(s * 8 + nt) * 32 + lane) * 16);
            }
#pragma unroll
            for (int m = 0; m < MT; m++)
#pragma unroll
                for (int n = 0; n < NT; n++) {
                    mma16816(acc[m][n], a_h[m], bq[n]);          // ah*bh
                    mma16816(acc[m][n], a_h[m], bq[n] + 2);      // ah*bl
                    mma16816(acc[m][n], a_l[m], bq[n]);          // al*bh
                }
        }
        __syncthreads();
    }

    // epilogue: bias + relu + hi/lo split + NHWC store
#pragma unroll
    for (int m = 0; m < MT; m++) {
        int pr0 = p0 + wm * (MT * 16) + m * 16 + (lane >> 2);
#pragma unroll
        for (int n = 0; n < NT; n++) {
            int oc = (wn * NT + n) * 8 + (lane & 3) * 2;
            float bs0 = sbias[oc], bs1 = sbias[oc + 1];
#pragma unroll
            for (int half = 0; half < 2; half++) {
                int pr = pr0 + half * 8;
                float v0 = fmaxf(acc[m][n][half * 2 + 0] + bs0, 0.f);
                float v1 = fmaxf(acc[m][n][half * 2 + 1] + bs1, 0.f);
                uint32_t lo, hi = splitp(v0, v1, lo);
                size_t off = ((size_t)b * HH + pr) * 64 + oc;
                *(uint32_t*)(outh + off) = hi;
                *(uint32_t*)(outl + off) = lo;
            }
        }
    }
}

// ---------------- 2x2 maxpool (NHWC hi/lo) ----------------
__global__ void maxpool_bf(const bf* __restrict__ ih, const bf* __restrict__ il,
                           bf* __restrict__ oh, bf* __restrict__ ol, int H)
{
    int Wo = H >> 1;
    int total = B * Wo * Wo * 64;
    int idx = blockIdx.x * 256 + threadIdx.x;
    if (idx >= total) return;
    int c = idx & 63, t = idx >> 6;
    int xo = t % Wo; t /= Wo;
    int yo = t % Wo; int b = t / Wo;
    size_t base = (((size_t)b * H + 2 * yo) * H + 2 * xo) * 64 + c;
    size_t rs = (size_t)H * 64;
    float v = fmaxf(fmaxf(joinv(ih[base], il[base]), joinv(ih[base + 64], il[base + 64])),
                    fmaxf(joinv(ih[base + rs], il[base + rs]), joinv(ih[base + rs + 64], il[base + rs + 64])));
    bf h = __float2bfloat16(v);
    oh[idx] = h;
    ol[idx] = __float2bfloat16(v - __bfloat162float(h));
}

// ---------------- bilinear x2 upsample + concat ----------------
__global__ void upconcat_bf(const bf* __restrict__ ih, const bf* __restrict__ il,
                            const bf* __restrict__ skh, const bf* __restrict__ skl,
                            bf* __restrict__ oh, bf* __restrict__ ol, int H)
{
    int Ho = H * 2;
    int total = B * Ho * Ho * 128;
    int idx = blockIdx.x * 256 + threadIdx.x;
    if (idx >= total) return;
    int c = idx & 127, t = idx >> 7;
    int xo = t % Ho; t /= Ho;
    int yo = t % Ho; int b = t / Ho;
    if (c >= 64) {
        size_t s = (((size_t)b * Ho + yo) * Ho + xo) * 64 + (c - 64);
        oh[idx] = skh[s];
        ol[idx] = skl[s];
        return;
    }
    float ys = (float)yo * (float)(H - 1) / (float)(Ho - 1);
    float xs = (float)xo * (float)(H - 1) / (float)(Ho - 1);
    int y0 = (int)floorf(ys); int y1 = min(y0 + 1, H - 1);
    int x0 = (int)floorf(xs); int x1 = min(x0 + 1, H - 1);
    float wy = ys - (float)y0, wx = xs - (float)x0;
    const bf* ph = ih + (size_t)b * H * H * 64 + c;
    const bf* pl = il + (size_t)b * H * H * 64 + c;
#define AT(y, x) joinv(ph[((size_t)(y) * H + (x)) * 64], pl[((size_t)(y) * H + (x)) * 64])
    float r0 = AT(y0, x0) * (1.f - wy) + AT(y1, x0) * wy;
    float r1 = AT(y0, x1) * (1.f - wy) + AT(y1, x1) * wy;
#undef AT
    float v = r0 * (1.f - wx) + r1 * wx;
    bf h = __float2bfloat16(v);
    oh[idx] = h;
    ol[idx] = __float2bfloat16(v - __bfloat162float(h));
}

// ---------------- final 1x1 conv (64->2) + residual, NHWC ----------------
__global__ void final_bf(const bf* __restrict__ ih, const bf* __restrict__ il,
                         const float* __restrict__ zf, const float* __restrict__ wbuf,
                         float* __restrict__ out)
{
    __shared__ float sw[130];
    int b = blockIdx.y, tid = threadIdx.x;
    const float* wb = wbuf + (size_t)b * OUTD;
    if (tid < 128) sw[tid] = wb[590976 + tid];
    else if (tid < 130) sw[tid] = wb[592000 + (tid - 128)];
    __syncthreads();
    int hw = blockIdx.x * 256 + tid;
    const bf* ph = ih + ((size_t)b * 65536 + hw) * 64;
    const bf* pl = il + ((size_t)b * 65536 + hw) * 64;
    float a0 = sw[128], a1 = sw[129];
#pragma unroll 16
    for (int c = 0; c < 64; c++) {
        float v = joinv(ph[c], pl[c]);
        a0 = fmaf(v, sw[c], a0);
        a1 = fmaf(v, sw[64 + c], a1);
    }
    size_t o = ((size_t)b * 65536 + hw) * 2;
    out[o] = zf[o] + a0;
    out[o + 1] = zf[o + 1] + a1;
}

// ---------------- host ----------------
static const int WMh[13] = {0, 36864, 73728, 110592, 147456, 184320, 221184, 258048,
                            331776, 368640, 442368, 479232, 552960};
static const int CINh[13] = {64, 64, 64, 64, 64, 64, 64, 128, 64, 128, 64, 128, 64};
#define SMEM_T256 163840
#define SMEM_T128 98304

static inline void launch_mm(const bf* ih, const bf* il, bf* oh, bf* ol,
                             const float* pw, int layer, int H, int lgH)
{
    int wmoff = WMh[layer - 1];
    int boff = 591104 + 64 * layer;
    int cin = CINh[layer - 1];
    if (H >= 128) {
        dim3 gs((H * H) / 256, 1, B);
        if (cin == 64)
            convmm_kernel<64, 256><<<gs, 512, SMEM_T256>>>(ih, il, oh, ol, pw, wmoff, boff, H, lgH);
        else
            convmm_kernel<128, 256><<<gs, 512, SMEM_T256>>>(ih, il, oh, ol, pw, wmoff, boff, H, lgH);
    } else {
        dim3 gs((H * H) / 128, 1, B);
        if (cin == 64)
            convmm_kernel<64, 128><<<gs, 256, SMEM_T128>>>(ih, il, oh, ol, pw, wmoff, boff, H, lgH);
        else
            convmm_kernel<128, 128><<<gs, 256, SMEM_T128>>>(ih, il, oh, ol, pw, wmoff, boff, H, lgH);
    }
}

extern "C" void kernel_launch(void* const* d_in, const int* in_sizes, int n_in,
                              void* d_out, int out_size)
{
    const float* zf = (const float*)d_in[0];
    const float* hp = (const float*)d_in[2];
    const float* W1 = (const float*)d_in[3];
    const float* b1 = (const float*)d_in[4];
    const float* W2 = (const float*)d_in[5];
    const float* b2 = (const float*)d_in[6];
    const float* Wo = (const float*)d_in[7];
    const float* bo = (const float*)d_in[8];
    float* out = (float*)d_out;
    float* l1 = out + (size_t)B * 131072;

    cudaFuncSetAttribute(convmm_kernel<64, 256>, cudaFuncAttributeMaxDynamicSharedMemorySize, SMEM_T256);
    cudaFuncSetAttribute(convmm_kernel<128, 256>, cudaFuncAttributeMaxDynamicSharedMemorySize, SMEM_T256);
    cudaFuncSetAttribute(convmm_kernel<64, 128>, cudaFuncAttributeMaxDynamicSharedMemorySize, SMEM_T128);
    cudaFuncSetAttribute(convmm_kernel<128, 128>, cudaFuncAttributeMaxDynamicSharedMemorySize, SMEM_T128);

    float* pW;
    bf *Ah, *Al, *Bh, *Bl, *S1h, *S1l, *S2h, *S2l, *S3h, *S3l;
    cudaGetSymbolAddress((void**)&pW, g_w);
    cudaGetSymbolAddress((void**)&Ah, g_Ah);
    cudaGetSymbolAddress((void**)&Al, g_Al);
    cudaGetSymbolAddress((void**)&Bh, g_Bh);
    cudaGetSymbolAddress((void**)&Bl, g_Bl);
    cudaGetSymbolAddress((void**)&S1h, g_S1h);
    cudaGetSymbolAddress((void**)&S1l, g_S1l);
    cudaGetSymbolAddress((void**)&S2h, g_S2h);
    cudaGetSymbolAddress((void**)&S2l, g_S2l);
    cudaGetSymbolAddress((void**)&S3h, g_S3h);
    cudaGetSymbolAddress((void**)&S3l, g_S3l);

    hyper1_kernel<<<1, 256>>>(hp, W1, b1, W2, b2, l1);
    weightgen_kernel<<<(OUTD + 255) / 256, 256>>>(Wo, bo, l1);
    repack0_kernel<<<(B * 576 + 255) / 256, 256>>>();
    repack_mm_kernel<<<(B * WMTOT + 255) / 256, 256>>>();

    // encoder
    conv0_kernel<<<dim3(64, 4, B), 256>>>(zf, Ah, Al, pW);
    launch_mm(Ah, Al, S1h, S1l, pW, 1, 256, 8);
    { int n = B * 128 * 128 * 64; maxpool_bf<<<(n + 255) / 256, 256>>>(S1h, S1l, Bh, Bl, 256); }
    launch_mm(Bh, Bl, Ah, Al, pW, 2, 128, 7);
    launch_mm(Ah, Al, S2h, S2l, pW, 3, 128, 7);
    { int n = B * 64 * 64 * 64; maxpool_bf<<<(n + 255) / 256, 256>>>(S2h, S2l, Bh, Bl, 128); }
    launch_mm(Bh, Bl, Ah, Al, pW, 4, 64, 6);
    launch_mm(Ah, Al, S3h, S3l, pW, 5, 64, 6);
    { int n = B * 32 * 32 * 64; maxpool_bf<<<(n + 255) / 256, 256>>>(S3h, S3l, Bh, Bl, 64); }
    launch_mm(Bh, Bl, Ah, Al, pW, 6, 32, 5);
    launch_mm(Ah, Al, Bh, Bl, pW, 7, 32, 5);

    // decoder
    { int n = B * 64 * 64 * 128; upconcat_bf<<<(n + 255) / 256, 256>>>(Bh, Bl, S3h, S3l, Ah, Al, 32); }
    launch_mm(Ah, Al, Bh, Bl, pW, 8, 64, 6);
    launch_mm(Bh, Bl, Ah, Al, pW, 9, 64, 6);
    { int n = B * 128 * 128 * 128; upconcat_bf<<<(n + 255) / 256, 256>>>(Ah, Al, S2h, S2l, Bh, Bl, 64); }
    launch_mm(Bh, Bl, Ah, Al, pW, 10, 128, 7);
    launch_mm(Ah, Al, Bh, Bl, pW, 11, 128, 7);
    { int n = B * 256 * 256 * 128; upconcat_bf<<<(n + 255) / 256, 256>>>(Bh, Bl, S1h, S1l, Ah, Al, 128); }
    launch_mm(Ah, Al, Bh, Bl, pW, 12, 256, 8);
    launch_mm(Bh, Bl, Ah, Al, pW, 13, 256, 8);

    final_bf<<<dim3(256, B), 256>>>(Ah, Al, zf, pW, out);
}

// round 12
// speedup vs baseline: 1.1249x; 1.1249x over previous
#include <cuda_runtime.h>
#include <cuda_bf16.h>
#include <math.h>
#include <stdint.h>

#define B 8
#define OUTD 592002
#define WMTOT 589824
typedef __nv_bfloat16 bf;

// ---------------- device globals ----------------
__device__ float g_w[(size_t)B * OUTD];
__device__ float g_h2[B * 32];
__device__ __align__(16) float2 g_wp0[(size_t)B * 640];
__device__ __align__(16) bf g_wmc[(size_t)B * WMTOT * 2];   // interleaved hi/lo mma weights
__device__ __align__(16) bf g_Ah[(size_t)B * 128 * 65536];
__device__ __align__(16) bf g_Al[(size_t)B * 128 * 65536];
__device__ __align__(16) bf g_Bh[(size_t)B * 128 * 65536];
__device__ __align__(16) bf g_Bl[(size_t)B * 128 * 65536];
__device__ __align__(16) bf g_S1h[(size_t)B * 64 * 65536];
__device__ __align__(16) bf g_S1l[(size_t)B * 64 * 65536];
__device__ __align__(16) bf g_S2h[(size_t)B * 64 * 16384];
__device__ __align__(16) bf g_S2l[(size_t)B * 64 * 16384];
__device__ __align__(16) bf g_S3h[(size_t)B * 64 * 4096];
__device__ __align__(16) bf g_S3l[(size_t)B * 64 * 4096];

__constant__ int cWM[13] = {0, 36864, 73728, 110592, 147456, 184320, 221184, 258048,
                            331776, 368640, 442368, 479232, 552960};
__constant__ int cK2[13] = {1152, 38016, 74880, 111744, 148608, 185472, 222336, 259200,
                            332928, 369792, 443520, 480384, 554112};
__constant__ int cCIN2[13] = {64, 64, 64, 64, 64, 64, 64, 128, 64, 128, 64, 128, 64};

// ---------------- helpers ----------------
__device__ __forceinline__ void fma2(unsigned long long& a, unsigned long long x, unsigned long long w)
{ asm("fma.rn.f32x2 %0, %1, %2, %0;" : "+l"(a) : "l"(x), "l"(w)); }
__device__ __forceinline__ unsigned long long pack2b(float a)
{ unsigned long long r; asm("mov.b64 %0, {%1, %1};" : "=l"(r) : "f"(a)); return r; }
__device__ __forceinline__ float2 unpack2(unsigned long long v)
{ float2 r; asm("mov.b64 {%0, %1}, %2;" : "=f"(r.x), "=f"(r.y) : "l"(v)); return r; }
__device__ __forceinline__ void cp16(uint32_t d, const void* s)
{ asm volatile("cp.async.cg.shared.global [%0], [%1], 16;" :: "r"(d), "l"(s) : "memory"); }
__device__ __forceinline__ void cp16z(uint32_t d, const void* s, int sz)
{ asm volatile("cp.async.cg.shared.global [%0], [%1], 16, %2;" :: "r"(d), "l"(s), "r"(sz) : "memory"); }
__device__ __forceinline__ void cp_commit()
{ asm volatile("cp.async.commit_group;" ::: "memory"); }
__device__ __forceinline__ void cp_wait1()
{ asm volatile("cp.async.wait_group 1;" ::: "memory"); }
__device__ __forceinline__ void cp_wait0()
{ asm volatile("cp.async.wait_group 0;" ::: "memory"); }
__device__ __forceinline__ float joinv(bf h, bf l)
{ return __bfloat162float(h) + __bfloat162float(l); }
__device__ __forceinline__ uint32_t splitp(float v0, float v1, uint32_t& lo)
{
    bf h0 = __float2bfloat16(v0), h1 = __float2bfloat16(v1);
    bf l0 = __float2bfloat16(v0 - __bfloat162float(h0));
    bf l1 = __float2bfloat16(v1 - __bfloat162float(h1));
    lo = (uint32_t)__bfloat16_as_ushort(l0) | ((uint32_t)__bfloat16_as_ushort(l1) << 16);
    return (uint32_t)__bfloat16_as_ushort(h0) | ((uint32_t)__bfloat16_as_ushort(h1) << 16);
}
__device__ __forceinline__ void ldsm4(uint32_t* r, uint32_t a)
{
    asm volatile("ldmatrix.sync.aligned.m8n8.x4.shared.b16 {%0,%1,%2,%3}, [%4];"
                 : "=r"(r[0]), "=r"(r[1]), "=r"(r[2]), "=r"(r[3]) : "r"(a));
}
__device__ __forceinline__ void lds128(uint32_t* v, uint32_t a)
{
    asm volatile("ld.shared.v4.b32 {%0,%1,%2,%3}, [%4];"
                 : "=r"(v[0]), "=r"(v[1]), "=r"(v[2]), "=r"(v[3]) : "r"(a));
}
__device__ __forceinline__ void mma16816(float* d, const uint32_t* a, const uint32_t* bq)
{
    asm volatile("mma.sync.aligned.m16n8k16.row.col.f32.bf16.bf16.f32 "
        "{%0,%1,%2,%3}, {%4,%5,%6,%7}, {%8,%9}, {%0,%1,%2,%3};"
        : "+f"(d[0]), "+f"(d[1]), "+f"(d[2]), "+f"(d[3])
        : "r"(a[0]), "r"(a[1]), "r"(a[2]), "r"(a[3]), "r"(bq[0]), "r"(bq[1]));
}

// ---------------- hypernet ----------------
__global__ void hyper1_kernel(const float* __restrict__ hp, const float* __restrict__ W1,
                              const float* __restrict__ b1, const float* __restrict__ W2,
                              const float* __restrict__ b2, float* __restrict__ l1)
{
    __shared__ float h1[B][32];
    int b = threadIdx.x >> 5, i = threadIdx.x & 31;
    if (threadIdx.x < B) l1[threadIdx.x] = 0.f;
    h1[b][i] = hp[b] * W1[i] + b1[i];
    __syncthreads();
    float a = b2[i];
#pragma unroll
    for (int k = 0; k < 32; k++) a += h1[b][k] * W2[i * 32 + k];
    g_h2[b * 32 + i] = a;
}

__global__ void weightgen_kernel(const float* __restrict__ Wo, const float* __restrict__ bo,
                                 float* __restrict__ l1out)
{
    __shared__ float sh2[B * 32];
    __shared__ float wsum[8][B];
    int tid = threadIdx.x;
    sh2[tid] = g_h2[tid];
    __syncthreads();
    int j = blockIdx.x * 256 + tid;
    float s[B];
#pragma unroll
    for (int b = 0; b < B; b++) s[b] = 0.f;
    if (j < OUTD) {
        float wr[32];
        const float* row = Wo + (size_t)j * 32;
#pragma unroll
        for (int i = 0; i < 32; i++) wr[i] = row[i];
        float bj = bo[j];
#pragma unroll
        for (int b = 0; b < B; b++) {
            float a = bj;
#pragma unroll
            for (int i = 0; i < 32; i++) a += wr[i] * sh2[b * 32 + i];
            float w = tanhf(a);
            g_w[(size_t)b * OUTD + j] = w;
            s[b] = fabsf(w);
        }
    }
    int warp = tid >> 5, lane = tid & 31;
#pragma unroll
    for (int b = 0; b < B; b++) {
        float v = s[b];
        for (int o = 16; o > 0; o >>= 1) v += __shfl_xor_sync(0xFFFFFFFFu, v, o);
        if (lane == 0) wsum[warp][b] = v;
    }
    __syncthreads();
    if (tid < B) {
        float a = 0.f;
#pragma unroll
        for (int w = 0; w < 8; w++) a += wsum[w][tid];
        atomicAdd(&l1out[tid], a);
    }
}

// ---------------- repack layer0 (fp32 pairs) ----------------
__global__ void repack0_kernel()
{
    int e = blockIdx.x * 256 + threadIdx.x;
    if (e >= B * 576) return;
    int b = e / 576, q = e - b * 576;
    int c = q / 288, t = q - c * 288, ocp = t / 9, k = t - ocp * 9;
    const float* wb = g_w + (size_t)b * OUTD;
    g_wp0[(size_t)b * 640 + (c * 32 + ocp) * 10 + k] =
        make_float2(wb[((2 * ocp) * 2 + c) * 9 + k], wb[((2 * ocp + 1) * 2 + c) * 9 + k]);
}

// ---------------- repack layers 1..13: interleaved hi/lo mma-B fragments --------
// chunk g: per lane-quad 16B = [hi(e0..3) | lo(e0..3)]
__global__ void repack_mm_kernel()
{
    int e = blockIdx.x * 256 + threadIdx.x;
    if (e >= B * WMTOT) return;
    int b = e / WMTOT, r = e - b * WMTOT;
    int l = 0;
#pragma unroll
    for (int i = 1; i < 13; i++)
        if (r >= cWM[i]) l = i;
    int rp = r - cWM[l];
    int cin = cCIN2[l], cblk = cin >> 6;
    int g = rp >> 12, idx = rp & 4095;
    int kk = g / cblk, cb = g - kk * cblk;
    int h = idx & 1, j2 = (idx >> 1) & 1, lane = (idx >> 2) & 31;
    int t = (idx >> 7) & 7, s = idx >> 10;
    int oc = t * 8 + (lane >> 2);
    int c = cb * 64 + s * 16 + (lane & 3) * 2 + j2 * 8 + h;
    float w = g_w[(size_t)b * OUTD + cK2[l] + ((oc * cin + c) * 9 + kk)];
    bf hh = __float2bfloat16(w);
    bf ll = __float2bfloat16(w - __bfloat162float(hh));
    size_t dst = (size_t)b * WMTOT * 2 + (size_t)cWM[l] * 2
               + (size_t)g * 8192 + (size_t)(idx >> 2) * 8 + (j2 * 2 + h);
    g_wmc[dst] = hh;
    g_wmc[dst + 4] = ll;
}

// ---------------- layer 0: CIN=2 fp32 conv, NHWC bf16 hi/lo out ----------------
__global__ __launch_bounds__(256) void conv0_kernel(
    const float* __restrict__ zf, bf* __restrict__ oh, bf* __restrict__ ol,
    const float* __restrict__ wbuf)
{
    __shared__ float sIn[2 * 1156];
    __shared__ float2 sW[2 * 72];
    int b = blockIdx.z, ocg = blockIdx.y;
    int ty0 = (blockIdx.x >> 3) << 5, tx0 = (blockIdx.x & 7) << 5;
    int tid = threadIdx.x, tx = tid & 15, ty = tid >> 4;
    const float* inb = zf + (size_t)b * 131072;
    const float2* wpb = g_wp0 + (size_t)b * 640;

    for (int idx = tid; idx < 2 * 1156; idx += 256) {
        int cs = idx / 1156, rem = idx - cs * 1156;
        int r = rem / 34, cc = rem - r * 34;
        int gy = ty0 - 1 + r, gx = tx0 - 1 + cc;
        float v = 0.f;
        if ((unsigned)gy < 256u && (unsigned)gx < 256u)
            v = inb[(((size_t)gy << 8) + gx) * 2 + cs];
        sIn[idx] = v;
    }
    for (int idx = tid; idx < 144; idx += 256) {
        int cs = idx / 72, rem = idx - cs * 72, ocp = rem / 9, k = rem - ocp * 9;
        sW[idx] = wpb[(cs * 32 + ocg * 8 + ocp) * 10 + k];
    }
    __syncthreads();

    unsigned long long acc[8][4];
#pragma unroll
    for (int i = 0; i < 8; i++)
#pragma unroll
        for (int p = 0; p < 4; p++) acc[i][p] = 0ull;
#pragma unroll
    for (int cs = 0; cs < 2; cs++) {
        float xi[16];
#pragma unroll
        for (int r = 0; r < 4; r++)
#pragma unroll
            for (int cc = 0; cc < 4; cc++)
                xi[r * 4 + cc] = sIn[cs * 1156 + (2 * ty + r) * 34 + 2 * tx + cc];
#pragma unroll
        for (int ky = 0; ky < 3; ky++)
#pragma unroll
            for (int kx = 0; kx < 3; kx++) {
                unsigned long long xx[4];
#pragma unroll
                for (int py = 0; py < 2; py++)
#pragma unroll
                    for (int px = 0; px < 2; px++)
                        xx[py * 2 + px] = pack2b(xi[(py + ky) * 4 + (px + kx)]);
#pragma unroll
                for (int o = 0; o < 8; o++) {
                    unsigned long long w =
                        *reinterpret_cast<const unsigned long long*>(&sW[cs * 72 + o * 9 + ky * 3 + kx]);
#pragma unroll
                    for (int p = 0; p < 4; p++) fma2(acc[o][p], xx[p], w);
                }
            }
    }
    const float* wb = wbuf + (size_t)b * OUTD;
#pragma unroll
    for (int o = 0; o < 8; o++) {
        int oc = (ocg * 8 + o) * 2;
        float b0 = wb[591104 + oc], b1 = wb[591104 + oc + 1];
#pragma unroll
        for (int py = 0; py < 2; py++)
#pragma unroll
            for (int px = 0; px < 2; px++) {
                float2 v = unpack2(acc[o][py * 2 + px]);
                float v0 = fmaxf(v.x + b0, 0.f), v1 = fmaxf(v.y + b1, 0.f);
                uint32_t lo, hi = splitp(v0, v1, lo);
                int p = (ty0 + 2 * ty + py) * 256 + tx0 + 2 * tx + px;
                size_t off = ((size_t)b * 65536 + p) * 64 + oc;
                *(uint32_t*)(oh + off) = hi;
                *(uint32_t*)(ol + off) = lo;
            }
    }
}

// ---------------- mma.sync conv layer v3: TM=128, ldmatrix A, LDS.128 B ----------
// 256 thr, 8 warps = 4 px-tiles(32px) x 2 oc-tiles(32oc).
// Buffer: AH 16K | AL 16K | Bc 16K (interleaved hi/lo). Double-buffered = 96K.
#define CMM_SMEM 98304
template<int CIN>
__global__ __launch_bounds__(256, 2) void convmm_kernel(
    const bf* __restrict__ inh, const bf* __restrict__ inl,
    bf* __restrict__ outh, bf* __restrict__ outl,
    const float* __restrict__ wbuf, int wmoff, int boff, int H, int lgH)
{
    constexpr int CBLK = CIN / 64;
    constexpr int G = 9 * CBLK;
    constexpr int MT = 2;       // m16 tiles per warp
    constexpr int NT = 4;       // n8 tiles per warp
    constexpr int BUF = 49152;

    extern __shared__ __align__(128) char smem[];
    __shared__ float sbias[64];
    const int tid = threadIdx.x;
    const int b = blockIdx.z;
    const int p0 = blockIdx.x * 128;
    const int HH = H * H;
    uint32_t sb0 = (uint32_t)__cvta_generic_to_shared(smem);

    if (tid < 64) sbias[tid] = wbuf[(size_t)b * OUTD + boff + tid];

    const bf* ibh = inh + (size_t)b * HH * CIN;
    const bf* ibl = inl + (size_t)b * HH * CIN;
    const char* wcb = (const char*)(g_wmc + (size_t)b * WMTOT * 2 + (size_t)wmoff * 2);

    const int ar = tid >> 1, aj0 = (tid & 1) * 4;
    const int py = p0 + ar;
    const int ay = py >> lgH, ax = py & (H - 1);

    auto stage = [&](int g, int buf) {
        const uint32_t AH = sb0 + buf * BUF, AL = AH + 16384, BB = AL + 16384;
        const int kk = g / CBLK, cb = g - kk * CBLK;
        const int dy = kk / 3 - 1, dx = kk - (kk / 3) * 3 - 1;
        int gy = ay + dy, gx = ax + dx;
        bool ok = ((unsigned)gy < (unsigned)H) && ((unsigned)gx < (unsigned)H);
        size_t q = ok ? ((size_t)(gy * H + gx) * CIN + cb * 64) : 0;
        const char* sh = (const char*)(ibh + q);
        const char* sl = (const char*)(ibl + q);
        int sz = ok ? 16 : 0;
        uint32_t ro = (uint32_t)ar * 128u, sw = (uint32_t)((ar & 7) << 4);
#pragma unroll
        for (int j = aj0; j < aj0 + 4; j++) {
            uint32_t o = ro + (((uint32_t)j * 16u) ^ sw);
            cp16z(AH + o, sh + j * 16, sz);
            cp16z(AL + o, sl + j * 16, sz);
        }
        const char* wg = wcb + (size_t)g * 16384;
#pragma unroll
        for (int j = 0; j < 4; j++) {
            uint32_t o = (uint32_t)(tid + j * 256) * 16u;
            cp16(BB + o, wg + o);
        }
    };

    const int lane = tid & 31, w = tid >> 5;
    const int wm = w & 3, wn = w >> 2;
    const int g4 = lane >> 3, li = lane & 7;

    float acc[MT][NT][4];
#pragma unroll
    for (int m = 0; m < MT; m++)
#pragma unroll
        for (int n = 0; n < NT; n++)
#pragma unroll
            for (int i = 0; i < 4; i++) acc[m][n][i] = 0.f;

    stage(0, 0);
    cp_commit();

    for (int g = 0; g < G; g++) {
        if (g + 1 < G) { stage(g + 1, (g + 1) & 1); cp_commit(); cp_wait1(); }
        else           { cp_wait0(); }
        __syncthreads();

        const uint32_t AH = sb0 + (g & 1) * BUF, AL = AH + 16384, BB = AL + 16384;

#pragma unroll
        for (int s = 0; s < 4; s++) {
            uint32_t a_h[MT][4], a_l[MT][4];
#pragma unroll
            for (int m = 0; m < MT; m++) {
                uint32_t row = (uint32_t)(wm * 32 + m * 16 + li + (g4 & 1) * 8);
                uint32_t kb = (uint32_t)(s * 32 + (g4 >> 1) * 16);
                uint32_t off = row * 128 + (kb ^ ((row & 7) << 4));
                ldsm4(a_h[m], AH + off);
                ldsm4(a_l[m], AL + off);
            }
            uint32_t bq[NT][4];
#pragma unroll
            for (int n = 0; n < NT; n++) {
                uint32_t nt = (uint32_t)(wn * NT + n);
                lds128(bq[n], BB + ((uint32_t)(s * 8 + nt) * 32 + lane) * 16);
            }
#pragma unroll
            for (int m = 0; m < MT; m++)
#pragma unroll
                for (int n = 0; n < NT; n++) {
                    mma16816(acc[m][n], a_h[m], bq[n]);          // ah*bh
                    mma16816(acc[m][n], a_h[m], bq[n] + 2);      // ah*bl
                    mma16816(acc[m][n], a_l[m], bq[n]);          // al*bh
                }
        }
        __syncthreads();
    }

    // epilogue: bias + relu + hi/lo split + NHWC store
#pragma unroll
    for (int m = 0; m < MT; m++) {
        int pr0 = p0 + wm * 32 + m * 16 + (lane >> 2);
#pragma unroll
        for (int n = 0; n < NT; n++) {
            int oc = (wn * NT + n) * 8 + (lane & 3) * 2;
            float bs0 = sbias[oc], bs1 = sbias[oc + 1];
#pragma unroll
            for (int half = 0; half < 2; half++) {
                int pr = pr0 + half * 8;
                float v0 = fmaxf(acc[m][n][half * 2 + 0] + bs0, 0.f);
                float v1 = fmaxf(acc[m][n][half * 2 + 1] + bs1, 0.f);
                uint32_t lo, hi = splitp(v0, v1, lo);
                size_t off = ((size_t)b * HH + pr) * 64 + oc;
                *(uint32_t*)(outh + off) = hi;
                *(uint32_t*)(outl + off) = lo;
            }
        }
    }
}

// ---------------- 2x2 maxpool (NHWC hi/lo) ----------------
__global__ void maxpool_bf(const bf* __restrict__ ih, const bf* __restrict__ il,
                           bf* __restrict__ oh, bf* __restrict__ ol, int H)
{
    int Wo = H >> 1;
    int total = B * Wo * Wo * 64;
    int idx = blockIdx.x * 256 + threadIdx.x;
    if (idx >= total) return;
    int c = idx & 63, t = idx >> 6;
    int xo = t % Wo; t /= Wo;
    int yo = t % Wo; int b = t / Wo;
    size_t base = (((size_t)b * H + 2 * yo) * H + 2 * xo) * 64 + c;
    size_t rs = (size_t)H * 64;
    float v = fmaxf(fmaxf(joinv(ih[base], il[base]), joinv(ih[base + 64], il[base + 64])),
                    fmaxf(joinv(ih[base + rs], il[base + rs]), joinv(ih[base + rs + 64], il[base + rs + 64])));
    bf h = __float2bfloat16(v);
    oh[idx] = h;
    ol[idx] = __float2bfloat16(v - __bfloat162float(h));
}

// ---------------- bilinear x2 upsample + concat ----------------
__global__ void upconcat_bf(const bf* __restrict__ ih, const bf* __restrict__ il,
                            const bf* __restrict__ skh, const bf* __restrict__ skl,
                            bf* __restrict__ oh, bf* __restrict__ ol, int H)
{
    int Ho = H * 2;
    int total = B * Ho * Ho * 128;
    int idx = blockIdx.x * 256 + threadIdx.x;
    if (idx >= total) return;
    int c = idx & 127, t = idx >> 7;
    int xo = t % Ho; t /= Ho;
    int yo = t % Ho; int b = t / Ho;
    if (c >= 64) {
        size_t s = (((size_t)b * Ho + yo) * Ho + xo) * 64 + (c - 64);
        oh[idx] = skh[s];
        ol[idx] = skl[s];
        return;
    }
    float ys = (float)yo * (float)(H - 1) / (float)(Ho - 1);
    float xs = (float)xo * (float)(H - 1) / (float)(Ho - 1);
    int y0 = (int)floorf(ys); int y1 = min(y0 + 1, H - 1);
    int x0 = (int)floorf(xs); int x1 = min(x0 + 1, H - 1);
    float wy = ys - (float)y0, wx = xs - (float)x0;
    const bf* ph = ih + (size_t)b * H * H * 64 + c;
    const bf* pl = il + (size_t)b * H * H * 64 + c;
#define AT(y, x) joinv(ph[((size_t)(y) * H + (x)) * 64], pl[((size_t)(y) * H + (x)) * 64])
    float r0 = AT(y0, x0) * (1.f - wy) + AT(y1, x0) * wy;
    float r1 = AT(y0, x1) * (1.f - wy) + AT(y1, x1) * wy;
#undef AT
    float v = r0 * (1.f - wx) + r1 * wx;
    bf h = __float2bfloat16(v);
    oh[idx] = h;
    ol[idx] = __float2bfloat16(v - __bfloat162float(h));
}

// ---------------- final 1x1 conv (64->2) + residual, NHWC ----------------
__global__ void final_bf(const bf* __restrict__ ih, const bf* __restrict__ il,
                         const float* __restrict__ zf, const float* __restrict__ wbuf,
                         float* __restrict__ out)
{
    __shared__ float sw[130];
    int b = blockIdx.y, tid = threadIdx.x;
    const float* wb = wbuf + (size_t)b * OUTD;
    if (tid < 128) sw[tid] = wb[590976 + tid];
    else if (tid < 130) sw[tid] = wb[592000 + (tid - 128)];
    __syncthreads();
    int hw = blockIdx.x * 256 + tid;
    const bf* ph = ih + ((size_t)b * 65536 + hw) * 64;
    const bf* pl = il + ((size_t)b * 65536 + hw) * 64;
    float a0 = sw[128], a1 = sw[129];
#pragma unroll 16
    for (int c = 0; c < 64; c++) {
        float v = joinv(ph[c], pl[c]);
        a0 = fmaf(v, sw[c], a0);
        a1 = fmaf(v, sw[64 + c], a1);
    }
    size_t o = ((size_t)b * 65536 + hw) * 2;
    out[o] = zf[o] + a0;
    out[o + 1] = zf[o + 1] + a1;
}

// ---------------- host ----------------
static const int WMh[13] = {0, 36864, 73728, 110592, 147456, 184320, 221184, 258048,
                            331776, 368640, 442368, 479232, 552960};
static const int CINh[13] = {64, 64, 64, 64, 64, 64, 64, 128, 64, 128, 64, 128, 64};

static inline void launch_mm(const bf* ih, const bf* il, bf* oh, bf* ol,
                             const float* pw, int layer, int H, int lgH)
{
    int wmoff = WMh[layer - 1];
    int boff = 591104 + 64 * layer;
    dim3 gs((H * H) / 128, 1, B);
    if (CINh[layer - 1] == 64)
        convmm_kernel<64><<<gs, 256, CMM_SMEM>>>(ih, il, oh, ol, pw, wmoff, boff, H, lgH);
    else
        convmm_kernel<128><<<gs, 256, CMM_SMEM>>>(ih, il, oh, ol, pw, wmoff, boff, H, lgH);
}

extern "C" void kernel_launch(void* const* d_in, const int* in_sizes, int n_in,
                              void* d_out, int out_size)
{
    const float* zf = (const float*)d_in[0];
    const float* hp = (const float*)d_in[2];
    const float* W1 = (const float*)d_in[3];
    const float* b1 = (const float*)d_in[4];
    const float* W2 = (const float*)d_in[5];
    const float* b2 = (const float*)d_in[6];
    const float* Wo = (const float*)d_in[7];
    const float* bo = (const float*)d_in[8];
    float* out = (float*)d_out;
    float* l1 = out + (size_t)B * 131072;

    cudaFuncSetAttribute(convmm_kernel<64>, cudaFuncAttributeMaxDynamicSharedMemorySize, CMM_SMEM);
    cudaFuncSetAttribute(convmm_kernel<128>, cudaFuncAttributeMaxDynamicSharedMemorySize, CMM_SMEM);

    float* pW;
    bf *Ah, *Al, *Bh, *Bl, *S1h, *S1l, *S2h, *S2l, *S3h, *S3l;
    cudaGetSymbolAddress((void**)&pW, g_w);
    cudaGetSymbolAddress((void**)&Ah, g_Ah);
    cudaGetSymbolAddress((void**)&Al, g_Al);
    cudaGetSymbolAddress((void**)&Bh, g_Bh);
    cudaGetSymbolAddress((void**)&Bl, g_Bl);
    cudaGetSymbolAddress((void**)&S1h, g_S1h);
    cudaGetSymbolAddress((void**)&S1l, g_S1l);
    cudaGetSymbolAddress((void**)&S2h, g_S2h);
    cudaGetSymbolAddress((void**)&S2l, g_S2l);
    cudaGetSymbolAddress((void**)&S3h, g_S3h);
    cudaGetSymbolAddress((void**)&S3l, g_S3l);

    hyper1_kernel<<<1, 256>>>(hp, W1, b1, W2, b2, l1);
    weightgen_kernel<<<(OUTD + 255) / 256, 256>>>(Wo, bo, l1);
    repack0_kernel<<<(B * 576 + 255) / 256, 256>>>();
    repack_mm_kernel<<<(B * WMTOT + 255) / 256, 256>>>();

    // encoder
    conv0_kernel<<<dim3(64, 4, B), 256>>>(zf, Ah, Al, pW);
    launch_mm(Ah, Al, S1h, S1l, pW, 1, 256, 8);
    { int n = B * 128 * 128 * 64; maxpool_bf<<<(n + 255) / 256, 256>>>(S1h, S1l, Bh, Bl, 256); }
    launch_mm(Bh, Bl, Ah, Al, pW, 2, 128, 7);
    launch_mm(Ah, Al, S2h, S2l, pW, 3, 128, 7);
    { int n = B * 64 * 64 * 64; maxpool_bf<<<(n + 255) / 256, 256>>>(S2h, S2l, Bh, Bl, 128); }
    launch_mm(Bh, Bl, Ah, Al, pW, 4, 64, 6);
    launch_mm(Ah, Al, S3h, S3l, pW, 5, 64, 6);
    { int n = B * 32 * 32 * 64; maxpool_bf<<<(n + 255) / 256, 256>>>(S3h, S3l, Bh, Bl, 64); }
    launch_mm(Bh, Bl, Ah, Al, pW, 6, 32, 5);
    launch_mm(Ah, Al, Bh, Bl, pW, 7, 32, 5);

    // decoder
    { int n = B * 64 * 64 * 128; upconcat_bf<<<(n + 255) / 256, 256>>>(Bh, Bl, S3h, S3l, Ah, Al, 32); }
    launch_mm(Ah, Al, Bh, Bl, pW, 8, 64, 6);
    launch_mm(Bh, Bl, Ah, Al, pW, 9, 64, 6);
    { int n = B * 128 * 128 * 128; upconcat_bf<<<(n + 255) / 256, 256>>>(Ah, Al, S2h, S2l, Bh, Bl, 64); }
    launch_mm(Bh, Bl, Ah, Al, pW, 10, 128, 7);
    launch_mm(Ah, Al, Bh, Bl, pW, 11, 128, 7);
    { int n = B * 256 * 256 * 128; upconcat_bf<<<(n + 255) / 256, 256>>>(Bh, Bl, S1h, S1l, Ah, Al, 128); }
    launch_mm(Ah, Al, Bh, Bl, pW, 12, 256, 8);
    launch_mm(Bh, Bl, Ah, Al, pW, 13, 256, 8);

    final_bf<<<dim3(256, B), 256>>>(Ah, Al, zf, pW, out);
}

// round 15
// speedup vs baseline: 1.2169x; 1.0818x over previous
#include <cuda_runtime.h>
#include <cuda_bf16.h>
#include <math.h>
#include <stdint.h>

#define B 8
#define OUTD 592002
#define WMTOT 589824
typedef __nv_bfloat16 bf;

// ---------------- device globals ----------------
__device__ float g_w[(size_t)B * OUTD];
__device__ float g_h2[B * 32];
__device__ __align__(16) float2 g_wp0[(size_t)B * 640];
__device__ __align__(16) bf g_wmc[(size_t)B * WMTOT * 2];   // interleaved hi/lo mma weights
__device__ __align__(16) bf g_Ah[(size_t)B * 128 * 65536];
__device__ __align__(16) bf g_Al[(size_t)B * 128 * 65536];
__device__ __align__(16) bf g_Bh[(size_t)B * 128 * 65536];
__device__ __align__(16) bf g_Bl[(size_t)B * 128 * 65536];
__device__ __align__(16) bf g_S1h[(size_t)B * 64 * 65536];
__device__ __align__(16) bf g_S1l[(size_t)B * 64 * 65536];
__device__ __align__(16) bf g_S2h[(size_t)B * 64 * 16384];
__device__ __align__(16) bf g_S2l[(size_t)B * 64 * 16384];
__device__ __align__(16) bf g_S3h[(size_t)B * 64 * 4096];
__device__ __align__(16) bf g_S3l[(size_t)B * 64 * 4096];

__constant__ int cWM[13] = {0, 36864, 73728, 110592, 147456, 184320, 221184, 258048,
                            331776, 368640, 442368, 479232, 552960};
__constant__ int cK2[13] = {1152, 38016, 74880, 111744, 148608, 185472, 222336, 259200,
                            332928, 369792, 443520, 480384, 554112};
__constant__ int cCIN2[13] = {64, 64, 64, 64, 64, 64, 64, 128, 64, 128, 64, 128, 64};

// ---------------- helpers ----------------
__device__ __forceinline__ void fma2(unsigned long long& a, unsigned long long x, unsigned long long w)
{ asm("fma.rn.f32x2 %0, %1, %2, %0;" : "+l"(a) : "l"(x), "l"(w)); }
__device__ __forceinline__ unsigned long long pack2b(float a)
{ unsigned long long r; asm("mov.b64 %0, {%1, %1};" : "=l"(r) : "f"(a)); return r; }
__device__ __forceinline__ float2 unpack2(unsigned long long v)
{ float2 r; asm("mov.b64 {%0, %1}, %2;" : "=f"(r.x), "=f"(r.y) : "l"(v)); return r; }
__device__ __forceinline__ void cp16(uint32_t d, const void* s)
{ asm volatile("cp.async.cg.shared.global [%0], [%1], 16;" :: "r"(d), "l"(s) : "memory"); }
__device__ __forceinline__ void cp16z(uint32_t d, const void* s, int sz)
{ asm volatile("cp.async.cg.shared.global [%0], [%1], 16, %2;" :: "r"(d), "l"(s), "r"(sz) : "memory"); }
__device__ __forceinline__ void cp_commit()
{ asm volatile("cp.async.commit_group;" ::: "memory"); }
__device__ __forceinline__ void cp_wait1()
{ asm volatile("cp.async.wait_group 1;" ::: "memory"); }
__device__ __forceinline__ void cp_wait0()
{ asm volatile("cp.async.wait_group 0;" ::: "memory"); }
__device__ __forceinline__ float joinv(bf h, bf l)
{ return __bfloat162float(h) + __bfloat162float(l); }
__device__ __forceinline__ uint32_t splitp(float v0, float v1, uint32_t& lo)
{
    bf h0 = __float2bfloat16(v0), h1 = __float2bfloat16(v1);
    bf l0 = __float2bfloat16(v0 - __bfloat162float(h0));
    bf l1 = __float2bfloat16(v1 - __bfloat162float(h1));
    lo = (uint32_t)__bfloat16_as_ushort(l0) | ((uint32_t)__bfloat16_as_ushort(l1) << 16);
    return (uint32_t)__bfloat16_as_ushort(h0) | ((uint32_t)__bfloat16_as_ushort(h1) << 16);
}
__device__ __forceinline__ void ldsm4(uint32_t* r, uint32_t a)
{
    asm volatile("ldmatrix.sync.aligned.m8n8.x4.shared.b16 {%0,%1,%2,%3}, [%4];"
                 : "=r"(r[0]), "=r"(r[1]), "=r"(r[2]), "=r"(r[3]) : "r"(a));
}
__device__ __forceinline__ void lds128(uint32_t* v, uint32_t a)
{
    asm volatile("ld.shared.v4.b32 {%0,%1,%2,%3}, [%4];"
                 : "=r"(v[0]), "=r"(v[1]), "=r"(v[2]), "=r"(v[3]) : "r"(a));
}
__device__ __forceinline__ void mma16816(float* d, const uint32_t* a, const uint32_t* bq)
{
    asm volatile("mma.sync.aligned.m16n8k16.row.col.f32.bf16.bf16.f32 "
        "{%0,%1,%2,%3}, {%4,%5,%6,%7}, {%8,%9}, {%0,%1,%2,%3};"
        : "+f"(d[0]), "+f"(d[1]), "+f"(d[2]), "+f"(d[3])
        : "r"(a[0]), "r"(a[1]), "r"(a[2]), "r"(a[3]), "r"(bq[0]), "r"(bq[1]));
}

// ---------------- hypernet ----------------
__global__ void hyper1_kernel(const float* __restrict__ hp, const float* __restrict__ W1,
                              const float* __restrict__ b1, const float* __restrict__ W2,
                              const float* __restrict__ b2, float* __restrict__ l1)
{
    __shared__ float h1[B][32];
    int b = threadIdx.x >> 5, i = threadIdx.x & 31;
    if (threadIdx.x < B) l1[threadIdx.x] = 0.f;
    h1[b][i] = hp[b] * W1[i] + b1[i];
    __syncthreads();
    float a = b2[i];
#pragma unroll
    for (int k = 0; k < 32; k++) a += h1[b][k] * W2[i * 32 + k];
    g_h2[b * 32 + i] = a;
}

__global__ void weightgen_kernel(const float* __restrict__ Wo, const float* __restrict__ bo,
                                 float* __restrict__ l1out)
{
    __shared__ float sh2[B * 32];
    __shared__ float wsum[8][B];
    int tid = threadIdx.x;
    sh2[tid] = g_h2[tid];
    __syncthreads();
    int j = blockIdx.x * 256 + tid;
    float s[B];
#pragma unroll
    for (int b = 0; b < B; b++) s[b] = 0.f;
    if (j < OUTD) {
        float wr[32];
        const float* row = Wo + (size_t)j * 32;
#pragma unroll
        for (int i = 0; i < 32; i++) wr[i] = row[i];
        float bj = bo[j];
#pragma unroll
        for (int b = 0; b < B; b++) {
            float a = bj;
#pragma unroll
            for (int i = 0; i < 32; i++) a += wr[i] * sh2[b * 32 + i];
            float w = tanhf(a);
            g_w[(size_t)b * OUTD + j] = w;
            s[b] = fabsf(w);
        }
    }
    int warp = tid >> 5, lane = tid & 31;
#pragma unroll
    for (int b = 0; b < B; b++) {
        float v = s[b];
        for (int o = 16; o > 0; o >>= 1) v += __shfl_xor_sync(0xFFFFFFFFu, v, o);
        if (lane == 0) wsum[warp][b] = v;
    }
    __syncthreads();
    if (tid < B) {
        float a = 0.f;
#pragma unroll
        for (int w = 0; w < 8; w++) a += wsum[w][tid];
        atomicAdd(&l1out[tid], a);
    }
}

// ---------------- repack layer0 (fp32 pairs) ----------------
__global__ void repack0_kernel()
{
    int e = blockIdx.x * 256 + threadIdx.x;
    if (e >= B * 576) return;
    int b = e / 576, q = e - b * 576;
    int c = q / 288, t = q - c * 288, ocp = t / 9, k = t - ocp * 9;
    const float* wb = g_w + (size_t)b * OUTD;
    g_wp0[(size_t)b * 640 + (c * 32 + ocp) * 10 + k] =
        make_float2(wb[((2 * ocp) * 2 + c) * 9 + k], wb[((2 * ocp + 1) * 2 + c) * 9 + k]);
}

// ---------------- repack layers 1..13: interleaved hi/lo mma-B fragments --------
__global__ void repack_mm_kernel()
{
    int e = blockIdx.x * 256 + threadIdx.x;
    if (e >= B * WMTOT) return;
    int b = e / WMTOT, r = e - b * WMTOT;
    int l = 0;
#pragma unroll
    for (int i = 1; i < 13; i++)
        if (r >= cWM[i]) l = i;
    int rp = r - cWM[l];
    int cin = cCIN2[l], cblk = cin >> 6;
    int g = rp >> 12, idx = rp & 4095;
    int kk = g / cblk, cb = g - kk * cblk;
    int h = idx & 1, j2 = (idx >> 1) & 1, lane = (idx >> 2) & 31;
    int t = (idx >> 7) & 7, s = idx >> 10;
    int oc = t * 8 + (lane >> 2);
    int c = cb * 64 + s * 16 + (lane & 3) * 2 + j2 * 8 + h;
    float w = g_w[(size_t)b * OUTD + cK2[l] + ((oc * cin + c) * 9 + kk)];
    bf hh = __float2bfloat16(w);
    bf ll = __float2bfloat16(w - __bfloat162float(hh));
    size_t dst = (size_t)b * WMTOT * 2 + (size_t)cWM[l] * 2
               + (size_t)g * 8192 + (size_t)(idx >> 2) * 8 + (j2 * 2 + h);
    g_wmc[dst] = hh;
    g_wmc[dst + 4] = ll;
}

// ---------------- layer 0: CIN=2 fp32 conv, NHWC bf16 hi/lo out ----------------
__global__ __launch_bounds__(256) void conv0_kernel(
    const float* __restrict__ zf, bf* __restrict__ oh, bf* __restrict__ ol,
    const float* __restrict__ wbuf)
{
    __shared__ float sIn[2 * 1156];
    __shared__ float2 sW[2 * 72];
    int b = blockIdx.z, ocg = blockIdx.y;
    int ty0 = (blockIdx.x >> 3) << 5, tx0 = (blockIdx.x & 7) << 5;
    int tid = threadIdx.x, tx = tid & 15, ty = tid >> 4;
    const float* inb = zf + (size_t)b * 131072;
    const float2* wpb = g_wp0 + (size_t)b * 640;

    for (int idx = tid; idx < 2 * 1156; idx += 256) {
        int cs = idx / 1156, rem = idx - cs * 1156;
        int r = rem / 34, cc = rem - r * 34;
        int gy = ty0 - 1 + r, gx = tx0 - 1 + cc;
        float v = 0.f;
        if ((unsigned)gy < 256u && (unsigned)gx < 256u)
            v = inb[(((size_t)gy << 8) + gx) * 2 + cs];
        sIn[idx] = v;
    }
    for (int idx = tid; idx < 144; idx += 256) {
        int cs = idx / 72, rem = idx - cs * 72, ocp = rem / 9, k = rem - ocp * 9;
        sW[idx] = wpb[(cs * 32 + ocg * 8 + ocp) * 10 + k];
    }
    __syncthreads();

    unsigned long long acc[8][4];
#pragma unroll
    for (int i = 0; i < 8; i++)
#pragma unroll
        for (int p = 0; p < 4; p++) acc[i][p] = 0ull;
#pragma unroll
    for (int cs = 0; cs < 2; cs++) {
        float xi[16];
#pragma unroll
        for (int r = 0; r < 4; r++)
#pragma unroll
            for (int cc = 0; cc < 4; cc++)
                xi[r * 4 + cc] = sIn[cs * 1156 + (2 * ty + r) * 34 + 2 * tx + cc];
#pragma unroll
        for (int ky = 0; ky < 3; ky++)
#pragma unroll
            for (int kx = 0; kx < 3; kx++) {
                unsigned long long xx[4];
#pragma unroll
                for (int py = 0; py < 2; py++)
#pragma unroll
                    for (int px = 0; px < 2; px++)
                        xx[py * 2 + px] = pack2b(xi[(py + ky) * 4 + (px + kx)]);
#pragma unroll
                for (int o = 0; o < 8; o++) {
                    unsigned long long w =
                        *reinterpret_cast<const unsigned long long*>(&sW[cs * 72 + o * 9 + ky * 3 + kx]);
#pragma unroll
                    for (int p = 0; p < 4; p++) fma2(acc[o][p], xx[p], w);
                }
            }
    }
    const float* wb = wbuf + (size_t)b * OUTD;
#pragma unroll
    for (int o = 0; o < 8; o++) {
        int oc = (ocg * 8 + o) * 2;
        float b0 = wb[591104 + oc], b1 = wb[591104 + oc + 1];
#pragma unroll
        for (int py = 0; py < 2; py++)
#pragma unroll
            for (int px = 0; px < 2; px++) {
                float2 v = unpack2(acc[o][py * 2 + px]);
                float v0 = fmaxf(v.x + b0, 0.f), v1 = fmaxf(v.y + b1, 0.f);
                uint32_t lo, hi = splitp(v0, v1, lo);
                int p = (ty0 + 2 * ty + py) * 256 + tx0 + 2 * tx + px;
                size_t off = ((size_t)b * 65536 + p) * 64 + oc;
                *(uint32_t*)(oh + off) = hi;
                *(uint32_t*)(ol + off) = lo;
            }
    }
}

// ---------------- small-H mma conv (H<=64) ----------------
#define CMM_SMEM 98304
template<int CIN>
__global__ __launch_bounds__(256, 2) void convmm_kernel(
    const bf* __restrict__ inh, const bf* __restrict__ inl,
    bf* __restrict__ outh, bf* __restrict__ outl,
    const float* __restrict__ wbuf, int wmoff, int boff, int H, int lgH)
{
    constexpr int CBLK = CIN / 64;
    constexpr int G = 9 * CBLK;
    constexpr int MT = 2, NT = 4;
    constexpr int BUF = 49152;

    extern __shared__ __align__(128) char smem[];
    __shared__ float sbias[64];
    const int tid = threadIdx.x;
    const int b = blockIdx.z;
    const int p0 = blockIdx.x * 128;
    const int HH = H * H;
    uint32_t sb0 = (uint32_t)__cvta_generic_to_shared(smem);

    if (tid < 64) sbias[tid] = wbuf[(size_t)b * OUTD + boff + tid];

    const bf* ibh = inh + (size_t)b * HH * CIN;
    const bf* ibl = inl + (size_t)b * HH * CIN;
    const char* wcb = (const char*)(g_wmc + (size_t)b * WMTOT * 2 + (size_t)wmoff * 2);

    const int ar = tid >> 1, aj0 = (tid & 1) * 4;
    const int py = p0 + ar;
    const int ay = py >> lgH, ax = py & (H - 1);

    auto stage = [&](int g, int buf) {
        const uint32_t AH = sb0 + buf * BUF, AL = AH + 16384, BB = AL + 16384;
        const int kk = g / CBLK, cb = g - kk * CBLK;
        const int dy = kk / 3 - 1, dx = kk - (kk / 3) * 3 - 1;
        int gy = ay + dy, gx = ax + dx;
        bool ok = ((unsigned)gy < (unsigned)H) && ((unsigned)gx < (unsigned)H);
        size_t q = ok ? ((size_t)(gy * H + gx) * CIN + cb * 64) : 0;
        const char* sh = (const char*)(ibh + q);
        const char* sl = (const char*)(ibl + q);
        int sz = ok ? 16 : 0;
        uint32_t ro = (uint32_t)ar * 128u, sw = (uint32_t)((ar & 7) << 4);
#pragma unroll
        for (int j = aj0; j < aj0 + 4; j++) {
            uint32_t o = ro + (((uint32_t)j * 16u) ^ sw);
            cp16z(AH + o, sh + j * 16, sz);
            cp16z(AL + o, sl + j * 16, sz);
        }
        const char* wg = wcb + (size_t)g * 16384;
#pragma unroll
        for (int j = 0; j < 4; j++) {
            uint32_t o = (uint32_t)(tid + j * 256) * 16u;
            cp16(BB + o, wg + o);
        }
    };

    const int lane = tid & 31, w = tid >> 5;
    const int wm = w & 3, wn = w >> 2;
    const int g4 = lane >> 3, li = lane & 7;

    float acc[MT][NT][4];
#pragma unroll
    for (int m = 0; m < MT; m++)
#pragma unroll
        for (int n = 0; n < NT; n++)
#pragma unroll
            for (int i = 0; i < 4; i++) acc[m][n][i] = 0.f;

    stage(0, 0);
    cp_commit();

    for (int g = 0; g < G; g++) {
        if (g + 1 < G) { stage(g + 1, (g + 1) & 1); cp_commit(); cp_wait1(); }
        else           { cp_wait0(); }
        __syncthreads();

        const uint32_t AH = sb0 + (g & 1) * BUF, AL = AH + 16384, BB = AL + 16384;

#pragma unroll
        for (int s = 0; s < 4; s++) {
            uint32_t a_h[MT][4], a_l[MT][4];
#pragma unroll
            for (int m = 0; m < MT; m++) {
                uint32_t row = (uint32_t)(wm * 32 + m * 16 + li + (g4 & 1) * 8);
                uint32_t kb = (uint32_t)(s * 32 + (g4 >> 1) * 16);
                uint32_t off = row * 128 + (kb ^ ((row & 7) << 4));
                ldsm4(a_h[m], AH + off);
                ldsm4(a_l[m], AL + off);
            }
            uint32_t bq[NT][4];
#pragma unroll
            for (int n = 0; n < NT; n++) {
                uint32_t nt = (uint32_t)(wn * NT + n);
                lds128(bq[n], BB + ((uint32_t)(s * 8 + nt) * 32 + lane) * 16);
            }
#pragma unroll
            for (int m = 0; m < MT; m++)
#pragma unroll
                for (int n = 0; n < NT; n++) {
                    mma16816(acc[m][n], a_h[m], bq[n]);
                    mma16816(acc[m][n], a_h[m], bq[n] + 2);
                    mma16816(acc[m][n], a_l[m], bq[n]);
                }
        }
        __syncthreads();
    }

#pragma unroll
    for (int m = 0; m < MT; m++) {
        int pr0 = p0 + wm * 32 + m * 16 + (lane >> 2);
#pragma unroll
        for (int n = 0; n < NT; n++) {
            int oc = (wn * NT + n) * 8 + (lane & 3) * 2;
            float bs0 = sbias[oc], bs1 = sbias[oc + 1];
#pragma unroll
            for (int half = 0; half < 2; half++) {
                int pr = pr0 + half * 8;
                float v0 = fmaxf(acc[m][n][half * 2 + 0] + bs0, 0.f);
                float v1 = fmaxf(acc[m][n][half * 2 + 1] + bs1, 0.f);
                uint32_t lo, hi = splitp(v0, v1, lo);
                size_t off = ((size_t)b * HH + pr) * 64 + oc;
                *(uint32_t*)(outh + off) = hi;
                *(uint32_t*)(outl + off) = lo;
            }
        }
    }
}

// ---------------- row-slab mma conv (H>=128): resident B, per-ky A slab ----------
#define CR_SMEM 215040
template<int CIN>
__global__ __launch_bounds__(256, 1) void convrow_kernel(
    const bf* __restrict__ inh, const bf* __restrict__ inl,
    bf* __restrict__ outh, bf* __restrict__ outl,
    const float* __restrict__ wbuf, int wmoff, int boff, int H, int lgH)
{
    constexpr int CBLK = CIN / 64;
    constexpr int ASZ = 33792;    // hi+lo per buffer
    extern __shared__ __align__(128) char smem[];
    __shared__ float sbias[64];
    const int tid = threadIdx.x;
    const int b = blockIdx.z;
    const int p0 = blockIdx.x * 128;
    const int HH = H * H;
    uint32_t sb0 = (uint32_t)__cvta_generic_to_shared(smem);
    const uint32_t BB = sb0;             // 147456 bytes
    const uint32_t AB = sb0 + 147456;    // 2 * ASZ

    if (tid < 64) sbias[tid] = wbuf[(size_t)b * OUTD + boff + tid];

    const bf* ibh = inh + (size_t)b * HH * CIN;
    const bf* ibl = inl + (size_t)b * HH * CIN;
    const char* wcb = (const char*)(g_wmc + (size_t)b * WMTOT * 2 + (size_t)wmoff * 2);

    const int y0 = p0 >> lgH;
    const int x0 = p0 & (H - 1);

    auto stageA = [&](int ky, int cb, int buf) {
        int y = y0 - 1 + ky;
        bool rok = (unsigned)y < (unsigned)H;
        uint32_t Ab = AB + (uint32_t)buf * ASZ;
        for (int idx = tid; idx < 1040; idx += 256) {
            int p = idx >> 3, j = idx & 7;
            int x = x0 - 1 + p;
            bool ok = rok && ((unsigned)x < (unsigned)H);
            const char* sh = (const char*)ibh;
            const char* sl = (const char*)ibl;
            if (ok) {
                size_t q = ((size_t)y * H + x) * CIN + cb * 64;
                sh = (const char*)(ibh + q) + j * 16;
                sl = (const char*)(ibl + q) + j * 16;
            }
            uint32_t o = (uint32_t)p * 128u + (((uint32_t)j * 16u) ^ (((uint32_t)p & 7u) << 4));
            int sz = ok ? 16 : 0;
            cp16z(Ab + o, sh, sz);
            cp16z(Ab + 16896 + o, sl, sz);
        }
    };
    auto stageB = [&](int ky, int cb) {
        for (int idx = tid; idx < 3072; idx += 256) {
            int tl = idx >> 10;
            uint32_t within = (uint32_t)(idx & 1023) * 16u;
            int t = ky * 3 + tl;
            int g = (CBLK == 1) ? t : (t * 2 + cb);
            cp16(BB + (uint32_t)t * 16384u + within, wcb + (size_t)g * 16384 + within);
        }
    };

    const int lane = tid & 31, w = tid >> 5;
    const int wm = w & 3, wn = w >> 2;   // 4 px-tiles x 2 oc-tiles
    const int g4 = lane >> 3, li = lane & 7;

    float acc[2][4][4];
#pragma unroll
    for (int m = 0; m < 2; m++)
#pragma unroll
        for (int n = 0; n < 4; n++)
#pragma unroll
            for (int i = 0; i < 4; i++) acc[m][n][i] = 0.f;

    for (int cb = 0; cb < CBLK; cb++) {
        stageA(0, cb, 0);
        stageB(0, cb);
        cp_commit();
        for (int ky = 0; ky < 3; ky++) {
            if (ky < 2) { stageA(ky + 1, cb, (ky + 1) & 1); stageB(ky + 1, cb); cp_commit(); cp_wait1(); }
            else        { cp_wait0(); }
            __syncthreads();
            uint32_t Ab = AB + (uint32_t)(ky & 1) * ASZ;
#pragma unroll
            for (int kx = 0; kx < 3; kx++) {
                uint32_t Bt = BB + (uint32_t)(ky * 3 + kx) * 16384u;
#pragma unroll
                for (int s = 0; s < 4; s++) {
                    uint32_t a_h[2][4], a_l[2][4];
#pragma unroll
                    for (int m = 0; m < 2; m++) {
                        uint32_t r = (uint32_t)(wm * 32 + m * 16 + li + (g4 & 1) * 8);
                        uint32_t si = r + (uint32_t)kx;
                        uint32_t off = si * 128 + (((uint32_t)(s * 32 + (g4 >> 1) * 16)) ^ ((si & 7) << 4));
                        ldsm4(a_h[m], Ab + off);
                        ldsm4(a_l[m], Ab + 16896 + off);
                    }
                    uint32_t bq[4][4];
#pragma unroll
                    for (int n = 0; n < 4; n++)
                        lds128(bq[n], Bt + ((uint32_t)((s * 8 + wn * 4 + n) * 32 + lane)) * 16);
#pragma unroll
                    for (int m = 0; m < 2; m++)
#pragma unroll
                        for (int n = 0; n < 4; n++) {
                            mma16816(acc[m][n], a_h[m], bq[n]);
                            mma16816(acc[m][n], a_h[m], bq[n] + 2);
                            mma16816(acc[m][n], a_l[m], bq[n]);
                        }
                }
            }
            __syncthreads();
        }
    }

    // epilogue
#pragma unroll
    for (int m = 0; m < 2; m++) {
        int pr0 = p0 + wm * 32 + m * 16 + (lane >> 2);
#pragma unroll
        for (int n = 0; n < 4; n++) {
            int oc = (wn * 4 + n) * 8 + (lane & 3) * 2;
            float bs0 = sbias[oc], bs1 = sbias[oc + 1];
#pragma unroll
            for (int half = 0; half < 2; half++) {
                int pr = pr0 + half * 8;
                float v0 = fmaxf(acc[m][n][half * 2 + 0] + bs0, 0.f);
                float v1 = fmaxf(acc[m][n][half * 2 + 1] + bs1, 0.f);
                uint32_t lo, hi = splitp(v0, v1, lo);
                size_t off = ((size_t)b * HH + pr) * 64 + oc;
                *(uint32_t*)(outh + off) = hi;
                *(uint32_t*)(outl + off) = lo;
            }
        }
    }
}

// ---------------- 2x2 maxpool (NHWC hi/lo) ----------------
__global__ void maxpool_bf(const bf* __restrict__ ih, const bf* __restrict__ il,
                           bf* __restrict__ oh, bf* __restrict__ ol, int H)
{
    int Wo = H >> 1;
    int total = B * Wo * Wo * 64;
    int idx = blockIdx.x * 256 + threadIdx.x;
    if (idx >= total) return;
    int c = idx & 63, t = idx >> 6;
    int xo = t % Wo; t /= Wo;
    int yo = t % Wo; int b = t / Wo;
    size_t base = (((size_t)b * H + 2 * yo) * H + 2 * xo) * 64 + c;
    size_t rs = (size_t)H * 64;
    float v = fmaxf(fmaxf(joinv(ih[base], il[base]), joinv(ih[base + 64], il[base + 64])),
                    fmaxf(joinv(ih[base + rs], il[base + rs]), joinv(ih[base + rs + 64], il[base + rs + 64])));
    bf h = __float2bfloat16(v);
    oh[idx] = h;
    ol[idx] = __float2bfloat16(v - __bfloat162float(h));
}

// ---------------- bilinear x2 upsample + concat ----------------
__global__ void upconcat_bf(const bf* __restrict__ ih, const bf* __restrict__ il,
                            const bf* __restrict__ skh, const bf* __restrict__ skl,
                            bf* __restrict__ oh, bf* __restrict__ ol, int H)
{
    int Ho = H * 2;
    int total = B * Ho * Ho * 128;
    int idx = blockIdx.x * 256 + threadIdx.x;
    if (idx >= total) return;
    int c = idx & 127, t = idx >> 7;
    int xo = t % Ho; t /= Ho;
    int yo = t % Ho; int b = t / Ho;
    if (c >= 64) {
        size_t s = (((size_t)b * Ho + yo) * Ho + xo) * 64 + (c - 64);
        oh[idx] = skh[s];
        ol[idx] = skl[s];
        return;
    }
    float ys = (float)yo * (float)(H - 1) / (float)(Ho - 1);
    float xs = (float)xo * (float)(H - 1) / (float)(Ho - 1);
    int y0 = (int)floorf(ys); int y1 = min(y0 + 1, H - 1);
    int x0 = (int)floorf(xs); int x1 = min(x0 + 1, H - 1);
    float wy = ys - (float)y0, wx = xs - (float)x0;
    const bf* ph = ih + (size_t)b * H * H * 64 + c;
    const bf* pl = il + (size_t)b * H * H * 64 + c;
#define AT(y, x) joinv(ph[((size_t)(y) * H + (x)) * 64], pl[((size_t)(y) * H + (x)) * 64])
    float r0 = AT(y0, x0) * (1.f - wy) + AT(y1, x0) * wy;
    float r1 = AT(y0, x1) * (1.f - wy) + AT(y1, x1) * wy;
#undef AT
    float v = r0 * (1.f - wx) + r1 * wx;
    bf h = __float2bfloat16(v);
    oh[idx] = h;
    ol[idx] = __float2bfloat16(v - __bfloat162float(h));
}

// ---------------- final 1x1 conv (64->2) + residual, NHWC ----------------
__global__ void final_bf(const bf* __restrict__ ih, const bf* __restrict__ il,
                         const float* __restrict__ zf, const float* __restrict__ wbuf,
                         float* __restrict__ out)
{
    __shared__ float sw[130];
    int b = blockIdx.y, tid = threadIdx.x;
    const float* wb = wbuf + (size_t)b * OUTD;
    if (tid < 128) sw[tid] = wb[590976 + tid];
    else if (tid < 130) sw[tid] = wb[592000 + (tid - 128)];
    __syncthreads();
    int hw = blockIdx.x * 256 + tid;
    const bf* ph = ih + ((size_t)b * 65536 + hw) * 64;
    const bf* pl = il + ((size_t)b * 65536 + hw) * 64;
    float a0 = sw[128], a1 = sw[129];
#pragma unroll 16
    for (int c = 0; c < 64; c++) {
        float v = joinv(ph[c], pl[c]);
        a0 = fmaf(v, sw[c], a0);
        a1 = fmaf(v, sw[64 + c], a1);
    }
    size_t o = ((size_t)b * 65536 + hw) * 2;
    out[o] = zf[o] + a0;
    out[o + 1] = zf[o + 1] + a1;
}

// ---------------- host ----------------
static const int WMh[13] = {0, 36864, 73728, 110592, 147456, 184320, 221184, 258048,
                            331776, 368640, 442368, 479232, 552960};
static const int CINh[13] = {64, 64, 64, 64, 64, 64, 64, 128, 64, 128, 64, 128, 64};

static inline void launch_mm(const bf* ih, const bf* il, bf* oh, bf* ol,
                             const float* pw, int layer, int H, int lgH)
{
    int wmoff = WMh[layer - 1];
    int boff = 591104 + 64 * layer;
    dim3 gs((H * H) / 128, 1, B);
    if (H >= 128) {
        if (CINh[layer - 1] == 64)
            convrow_kernel<64><<<gs, 256, CR_SMEM>>>(ih, il, oh, ol, pw, wmoff, boff, H, lgH);
        else
            convrow_kernel<128><<<gs, 256, CR_SMEM>>>(ih, il, oh, ol, pw, wmoff, boff, H, lgH);
    } else {
        if (CINh[layer - 1] == 64)
            convmm_kernel<64><<<gs, 256, CMM_SMEM>>>(ih, il, oh, ol, pw, wmoff, boff, H, lgH);
        else
            convmm_kernel<128><<<gs, 256, CMM_SMEM>>>(ih, il, oh, ol, pw, wmoff, boff, H, lgH);
    }
}

extern "C" void kernel_launch(void* const* d_in, const int* in_sizes, int n_in,
                              void* d_out, int out_size)
{
    const float* zf = (const float*)d_in[0];
    const float* hp = (const float*)d_in[2];
    const float* W1 = (const float*)d_in[3];
    const float* b1 = (const float*)d_in[4];
    const float* W2 = (const float*)d_in[5];
    const float* b2 = (const float*)d_in[6];
    const float* Wo = (const float*)d_in[7];
    const float* bo = (const float*)d_in[8];
    float* out = (float*)d_out;
    float* l1 = out + (size_t)B * 131072;

    cudaFuncSetAttribute(convmm_kernel<64>, cudaFuncAttributeMaxDynamicSharedMemorySize, CMM_SMEM);
    cudaFuncSetAttribute(convmm_kernel<128>, cudaFuncAttributeMaxDynamicSharedMemorySize, CMM_SMEM);
    cudaFuncSetAttribute(convrow_kernel<64>, cudaFuncAttributeMaxDynamicSharedMemorySize, CR_SMEM);
    cudaFuncSetAttribute(convrow_kernel<128>, cudaFuncAttributeMaxDynamicSharedMemorySize, CR_SMEM);

    float* pW;
    bf *Ah, *Al, *Bh, *Bl, *S1h, *S1l, *S2h, *S2l, *S3h, *S3l;
    cudaGetSymbolAddress((void**)&pW, g_w);
    cudaGetSymbolAddress((void**)&Ah, g_Ah);
    cudaGetSymbolAddress((void**)&Al, g_Al);
    cudaGetSymbolAddress((void**)&Bh, g_Bh);
    cudaGetSymbolAddress((void**)&Bl, g_Bl);
    cudaGetSymbolAddress((void**)&S1h, g_S1h);
    cudaGetSymbolAddress((void**)&S1l, g_S1l);
    cudaGetSymbolAddress((void**)&S2h, g_S2h);
    cudaGetSymbolAddress((void**)&S2l, g_S2l);
    cudaGetSymbolAddress((void**)&S3h, g_S3h);
    cudaGetSymbolAddress((void**)&S3l, g_S3l);

    hyper1_kernel<<<1, 256>>>(hp, W1, b1, W2, b2, l1);
    weightgen_kernel<<<(OUTD + 255) / 256, 256>>>(Wo, bo, l1);
    repack0_kernel<<<(B * 576 + 255) / 256, 256>>>();
    repack_mm_kernel<<<(B * WMTOT + 255) / 256, 256>>>();

    // encoder
    conv0_kernel<<<dim3(64, 4, B), 256>>>(zf, Ah, Al, pW);
    launch_mm(Ah, Al, S1h, S1l, pW, 1, 256, 8);
    { int n = B * 128 * 128 * 64; maxpool_bf<<<(n + 255) / 256, 256>>>(S1h, S1l, Bh, Bl, 256); }
    launch_mm(Bh, Bl, Ah, Al, pW, 2, 128, 7);
    launch_mm(Ah, Al, S2h, S2l, pW, 3, 128, 7);
    { int n = B * 64 * 64 * 64; maxpool_bf<<<(n + 255) / 256, 256>>>(S2h, S2l, Bh, Bl, 128); }
    launch_mm(Bh, Bl, Ah, Al, pW, 4, 64, 6);
    launch_mm(Ah, Al, S3h, S3l, pW, 5, 64, 6);
    { int n = B * 32 * 32 * 64; maxpool_bf<<<(n + 255) / 256, 256>>>(S3h, S3l, Bh, Bl, 64); }
    launch_mm(Bh, Bl, Ah, Al, pW, 6, 32, 5);
    launch_mm(Ah, Al, Bh, Bl, pW, 7, 32, 5);

    // decoder
    { int n = B * 64 * 64 * 128; upconcat_bf<<<(n + 255) / 256, 256>>>(Bh, Bl, S3h, S3l, Ah, Al, 32); }
    launch_mm(Ah, Al, Bh, Bl, pW, 8, 64, 6);
    launch_mm(Bh, Bl, Ah, Al, pW, 9, 64, 6);
    { int n = B * 128 * 128 * 128; upconcat_bf<<<(n + 255) / 256, 256>>>(Ah, Al, S2h, S2l, Bh, Bl, 64); }
    launch_mm(Bh, Bl, Ah, Al, pW, 10, 128, 7);
    launch_mm(Ah, Al, Bh, Bl, pW, 11, 128, 7);
    { int n = B * 256 * 256 * 128; upconcat_bf<<<(n + 255) / 256, 256>>>(Bh, Bl, S1h, S1l, Ah, Al, 128); }
    launch_mm(Ah, Al, Bh, Bl, pW, 12, 256, 8);
    launch_mm(Bh, Bl, Ah, Al, pW, 13, 256, 8);

    final_bf<<<dim3(256, B), 256>>>(Ah, Al, zf, pW, out);
}

// round 16
// speedup vs baseline: 1.2400x; 1.0190x over previous
#include <cuda_runtime.h>
#include <cuda_bf16.h>
#include <math.h>
#include <stdint.h>

#define B 8
#define OUTD 592002
#define WMTOT 589824
typedef __nv_bfloat16 bf;

// ---------------- device globals ----------------
__device__ float g_w[(size_t)B * OUTD];
__device__ float g_h2[B * 32];
__device__ __align__(16) float2 g_wp0[(size_t)B * 640];
__device__ __align__(16) bf g_wmc[(size_t)B * WMTOT * 2];   // interleaved hi/lo mma weights
__device__ __align__(16) bf g_Ah[(size_t)B * 128 * 65536];
__device__ __align__(16) bf g_Al[(size_t)B * 128 * 65536];
__device__ __align__(16) bf g_Bh[(size_t)B * 128 * 65536];
__device__ __align__(16) bf g_Bl[(size_t)B * 128 * 65536];
__device__ __align__(16) bf g_S1h[(size_t)B * 64 * 65536];
__device__ __align__(16) bf g_S1l[(size_t)B * 64 * 65536];
__device__ __align__(16) bf g_S2h[(size_t)B * 64 * 16384];
__device__ __align__(16) bf g_S2l[(size_t)B * 64 * 16384];
__device__ __align__(16) bf g_S3h[(size_t)B * 64 * 4096];
__device__ __align__(16) bf g_S3l[(size_t)B * 64 * 4096];

__constant__ int cWM[13] = {0, 36864, 73728, 110592, 147456, 184320, 221184, 258048,
                            331776, 368640, 442368, 479232, 552960};
__constant__ int cK2[13] = {1152, 38016, 74880, 111744, 148608, 185472, 222336, 259200,
                            332928, 369792, 443520, 480384, 554112};
__constant__ int cCIN2[13] = {64, 64, 64, 64, 64, 64, 64, 128, 64, 128, 64, 128, 64};

// ---------------- helpers ----------------
__device__ __forceinline__ void fma2(unsigned long long& a, unsigned long long x, unsigned long long w)
{ asm("fma.rn.f32x2 %0, %1, %2, %0;" : "+l"(a) : "l"(x), "l"(w)); }
__device__ __forceinline__ unsigned long long pack2b(float a)
{ unsigned long long r; asm("mov.b64 %0, {%1, %1};" : "=l"(r) : "f"(a)); return r; }
__device__ __forceinline__ float2 unpack2(unsigned long long v)
{ float2 r; asm("mov.b64 {%0, %1}, %2;" : "=f"(r.x), "=f"(r.y) : "l"(v)); return r; }
__device__ __forceinline__ void cp16(uint32_t d, const void* s)
{ asm volatile("cp.async.cg.shared.global [%0], [%1], 16;" :: "r"(d), "l"(s) : "memory"); }
__device__ __forceinline__ void cp16z(uint32_t d, const void* s, int sz)
{ asm volatile("cp.async.cg.shared.global [%0], [%1], 16, %2;" :: "r"(d), "l"(s), "r"(sz) : "memory"); }
__device__ __forceinline__ void cp_commit()
{ asm volatile("cp.async.commit_group;" ::: "memory"); }
__device__ __forceinline__ void cp_wait1()
{ asm volatile("cp.async.wait_group 1;" ::: "memory"); }
__device__ __forceinline__ void cp_wait0()
{ asm volatile("cp.async.wait_group 0;" ::: "memory"); }
__device__ __forceinline__ float joinv(bf h, bf l)
{ return __bfloat162float(h) + __bfloat162float(l); }
__device__ __forceinline__ uint32_t splitp(float v0, float v1, uint32_t& lo)
{
    bf h0 = __float2bfloat16(v0), h1 = __float2bfloat16(v1);
    bf l0 = __float2bfloat16(v0 - __bfloat162float(h0));
    bf l1 = __float2bfloat16(v1 - __bfloat162float(h1));
    lo = (uint32_t)__bfloat16_as_ushort(l0) | ((uint32_t)__bfloat16_as_ushort(l1) << 16);
    return (uint32_t)__bfloat16_as_ushort(h0) | ((uint32_t)__bfloat16_as_ushort(h1) << 16);
}
__device__ __forceinline__ void ldsm4(uint32_t* r, uint32_t a)
{
    asm volatile("ldmatrix.sync.aligned.m8n8.x4.shared.b16 {%0,%1,%2,%3}, [%4];"
                 : "=r"(r[0]), "=r"(r[1]), "=r"(r[2]), "=r"(r[3]) : "r"(a));
}
__device__ __forceinline__ void lds128(uint32_t* v, uint32_t a)
{
    asm volatile("ld.shared.v4.b32 {%0,%1,%2,%3}, [%4];"
                 : "=r"(v[0]), "=r"(v[1]), "=r"(v[2]), "=r"(v[3]) : "r"(a));
}
__device__ __forceinline__ void mma16816(float* d, const uint32_t* a, const uint32_t* bq)
{
    asm volatile("mma.sync.aligned.m16n8k16.row.col.f32.bf16.bf16.f32 "
        "{%0,%1,%2,%3}, {%4,%5,%6,%7}, {%8,%9}, {%0,%1,%2,%3};"
        : "+f"(d[0]), "+f"(d[1]), "+f"(d[2]), "+f"(d[3])
        : "r"(a[0]), "r"(a[1]), "r"(a[2]), "r"(a[3]), "r"(bq[0]), "r"(bq[1]));
}

// ---------------- hypernet ----------------
__global__ void hyper1_kernel(const float* __restrict__ hp, const float* __restrict__ W1,
                              const float* __restrict__ b1, const float* __restrict__ W2,
                              const float* __restrict__ b2, float* __restrict__ l1)
{
    __shared__ float h1[B][32];
    int b = threadIdx.x >> 5, i = threadIdx.x & 31;
    if (threadIdx.x < B) l1[threadIdx.x] = 0.f;
    h1[b][i] = hp[b] * W1[i] + b1[i];
    __syncthreads();
    float a = b2[i];
#pragma unroll
    for (int k = 0; k < 32; k++) a += h1[b][k] * W2[i * 32 + k];
    g_h2[b * 32 + i] = a;
}

// ---------------- weightgen + fused conv-weight repack ----------------
__global__ void weightgen_kernel(const float* __restrict__ Wo, const float* __restrict__ bo,
                                 float* __restrict__ l1out)
{
    __shared__ float sh2[B * 32];
    __shared__ float wsum[8][B];
    int tid = threadIdx.x;
    sh2[tid] = g_h2[tid];
    __syncthreads();
    int j = blockIdx.x * 256 + tid;
    float s[B];
#pragma unroll
    for (int b = 0; b < B; b++) s[b] = 0.f;
    if (j < OUTD) {
        float wr[32];
        const float* row = Wo + (size_t)j * 32;
#pragma unroll
        for (int i = 0; i < 32; i++) wr[i] = row[i];
        float bj = bo[j];
        float wv[B];
#pragma unroll
        for (int b = 0; b < B; b++) {
            float a = bj;
#pragma unroll
            for (int i = 0; i < 32; i++) a += wr[i] * sh2[b * 32 + i];
            float w = tanhf(a);
            g_w[(size_t)b * OUTD + j] = w;
            wv[b] = w;
            s[b] = fabsf(w);
        }
        // fused repack of conv weights (layers 1..13) into mma-B fragment order
        if (j >= 1152 && j < 590976) {
            int l = 0;
#pragma unroll
            for (int i = 1; i < 13; i++)
                if (j >= cK2[i]) l = i;
            int cin = cCIN2[l];
            int K9 = cin * 9;
            int rp = j - cK2[l];
            int oc = rp / K9;
            int rem = rp - oc * K9;
            int c = rem / 9;
            int kk = rem - c * 9;
            int cblk = cin >> 6, cb = c >> 6, cp = c & 63;
            int g = kk * cblk + cb;
            int s4 = cp >> 4, w4 = cp & 15;
            int jj = w4 >> 3, q = (w4 & 7) >> 1, h = w4 & 1;
            int lane2 = (oc & 7) * 4 + q, t = oc >> 3;
            size_t off = (size_t)cWM[l] * 2 + (size_t)g * 8192
                       + (size_t)((s4 * 8 + t) * 32 + lane2) * 8 + jj * 2 + h;
#pragma unroll
            for (int b = 0; b < B; b++) {
                bf hh = __float2bfloat16(wv[b]);
                bf ll = __float2bfloat16(wv[b] - __bfloat162float(hh));
                g_wmc[(size_t)b * WMTOT * 2 + off] = hh;
                g_wmc[(size_t)b * WMTOT * 2 + off + 4] = ll;
            }
        }
    }
    int warp = tid >> 5, lane = tid & 31;
#pragma unroll
    for (int b = 0; b < B; b++) {
        float v = s[b];
        for (int o = 16; o > 0; o >>= 1) v += __shfl_xor_sync(0xFFFFFFFFu, v, o);
        if (lane == 0) wsum[warp][b] = v;
    }
    __syncthreads();
    if (tid < B) {
        float a = 0.f;
#pragma unroll
        for (int w = 0; w < 8; w++) a += wsum[w][tid];
        atomicAdd(&l1out[tid], a);
    }
}

// ---------------- repack layer0 (fp32 pairs) ----------------
__global__ void repack0_kernel()
{
    int e = blockIdx.x * 256 + threadIdx.x;
    if (e >= B * 576) return;
    int b = e / 576, q = e - b * 576;
    int c = q / 288, t = q - c * 288, ocp = t / 9, k = t - ocp * 9;
    const float* wb = g_w + (size_t)b * OUTD;
    g_wp0[(size_t)b * 640 + (c * 32 + ocp) * 10 + k] =
        make_float2(wb[((2 * ocp) * 2 + c) * 9 + k], wb[((2 * ocp + 1) * 2 + c) * 9 + k]);
}

// ---------------- layer 0: CIN=2 fp32 conv, NHWC bf16 hi/lo out ----------------
__global__ __launch_bounds__(256) void conv0_kernel(
    const float* __restrict__ zf, bf* __restrict__ oh, bf* __restrict__ ol,
    const float* __restrict__ wbuf)
{
    __shared__ float sIn[2 * 1156];
    __shared__ float2 sW[2 * 72];
    int b = blockIdx.z, ocg = blockIdx.y;
    int ty0 = (blockIdx.x >> 3) << 5, tx0 = (blockIdx.x & 7) << 5;
    int tid = threadIdx.x, tx = tid & 15, ty = tid >> 4;
    const float* inb = zf + (size_t)b * 131072;
    const float2* wpb = g_wp0 + (size_t)b * 640;

    for (int idx = tid; idx < 2 * 1156; idx += 256) {
        int cs = idx / 1156, rem = idx - cs * 1156;
        int r = rem / 34, cc = rem - r * 34;
        int gy = ty0 - 1 + r, gx = tx0 - 1 + cc;
        float v = 0.f;
        if ((unsigned)gy < 256u && (unsigned)gx < 256u)
            v = inb[(((size_t)gy << 8) + gx) * 2 + cs];
        sIn[idx] = v;
    }
    for (int idx = tid; idx < 144; idx += 256) {
        int cs = idx / 72, rem = idx - cs * 72, ocp = rem / 9, k = rem - ocp * 9;
        sW[idx] = wpb[(cs * 32 + ocg * 8 + ocp) * 10 + k];
    }
    __syncthreads();

    unsigned long long acc[8][4];
#pragma unroll
    for (int i = 0; i < 8; i++)
#pragma unroll
        for (int p = 0; p < 4; p++) acc[i][p] = 0ull;
#pragma unroll
    for (int cs = 0; cs < 2; cs++) {
        float xi[16];
#pragma unroll
        for (int r = 0; r < 4; r++)
#pragma unroll
            for (int cc = 0; cc < 4; cc++)
                xi[r * 4 + cc] = sIn[cs * 1156 + (2 * ty + r) * 34 + 2 * tx + cc];
#pragma unroll
        for (int ky = 0; ky < 3; ky++)
#pragma unroll
            for (int kx = 0; kx < 3; kx++) {
                unsigned long long xx[4];
#pragma unroll
                for (int py = 0; py < 2; py++)
#pragma unroll
                    for (int px = 0; px < 2; px++)
                        xx[py * 2 + px] = pack2b(xi[(py + ky) * 4 + (px + kx)]);
#pragma unroll
                for (int o = 0; o < 8; o++) {
                    unsigned long long w =
                        *reinterpret_cast<const unsigned long long*>(&sW[cs * 72 + o * 9 + ky * 3 + kx]);
#pragma unroll
                    for (int p = 0; p < 4; p++) fma2(acc[o][p], xx[p], w);
                }
            }
    }
    const float* wb = wbuf + (size_t)b * OUTD;
#pragma unroll
    for (int o = 0; o < 8; o++) {
        int oc = (ocg * 8 + o) * 2;
        float b0 = wb[591104 + oc], b1 = wb[591104 + oc + 1];
#pragma unroll
        for (int py = 0; py < 2; py++)
#pragma unroll
            for (int px = 0; px < 2; px++) {
                float2 v = unpack2(acc[o][py * 2 + px]);
                float v0 = fmaxf(v.x + b0, 0.f), v1 = fmaxf(v.y + b1, 0.f);
                uint32_t lo, hi = splitp(v0, v1, lo);
                int p = (ty0 + 2 * ty + py) * 256 + tx0 + 2 * tx + px;
                size_t off = ((size_t)b * 65536 + p) * 64 + oc;
                *(uint32_t*)(oh + off) = hi;
                *(uint32_t*)(ol + off) = lo;
            }
    }
}

// ---------------- small-H mma conv (H<=64) ----------------
#define CMM_SMEM 98304
template<int CIN>
__global__ __launch_bounds__(256, 2) void convmm_kernel(
    const bf* __restrict__ inh, const bf* __restrict__ inl,
    bf* __restrict__ outh, bf* __restrict__ outl,
    const float* __restrict__ wbuf, int wmoff, int boff, int H, int lgH)
{
    constexpr int CBLK = CIN / 64;
    constexpr int G = 9 * CBLK;
    constexpr int MT = 2, NT = 4;
    constexpr int BUF = 49152;

    extern __shared__ __align__(128) char smem[];
    __shared__ float sbias[64];
    const int tid = threadIdx.x;
    const int b = blockIdx.z;
    const int p0 = blockIdx.x * 128;
    const int HH = H * H;
    uint32_t sb0 = (uint32_t)__cvta_generic_to_shared(smem);

    if (tid < 64) sbias[tid] = wbuf[(size_t)b * OUTD + boff + tid];

    const bf* ibh = inh + (size_t)b * HH * CIN;
    const bf* ibl = inl + (size_t)b * HH * CIN;
    const char* wcb = (const char*)(g_wmc + (size_t)b * WMTOT * 2 + (size_t)wmoff * 2);

    const int ar = tid >> 1, aj0 = (tid & 1) * 4;
    const int py = p0 + ar;
    const int ay = py >> lgH, ax = py & (H - 1);

    auto stage = [&](int g, int buf) {
        const uint32_t AH = sb0 + buf * BUF, AL = AH + 16384, BB = AL + 16384;
        const int kk = g / CBLK, cb = g - kk * CBLK;
        const int dy = kk / 3 - 1, dx = kk - (kk / 3) * 3 - 1;
        int gy = ay + dy, gx = ax + dx;
        bool ok = ((unsigned)gy < (unsigned)H) && ((unsigned)gx < (unsigned)H);
        size_t q = ok ? ((size_t)(gy * H + gx) * CIN + cb * 64) : 0;
        const char* sh = (const char*)(ibh + q);
        const char* sl = (const char*)(ibl + q);
        int sz = ok ? 16 : 0;
        uint32_t ro = (uint32_t)ar * 128u, sw = (uint32_t)((ar & 7) << 4);
#pragma unroll
        for (int j = aj0; j < aj0 + 4; j++) {
            uint32_t o = ro + (((uint32_t)j * 16u) ^ sw);
            cp16z(AH + o, sh + j * 16, sz);
            cp16z(AL + o, sl + j * 16, sz);
        }
        const char* wg = wcb + (size_t)g * 16384;
#pragma unroll
        for (int j = 0; j < 4; j++) {
            uint32_t o = (uint32_t)(tid + j * 256) * 16u;
            cp16(BB + o, wg + o);
        }
    };

    const int lane = tid & 31, w = tid >> 5;
    const int wm = w & 3, wn = w >> 2;
    const int g4 = lane >> 3, li = lane & 7;

    float acc[MT][NT][4];
#pragma unroll
    for (int m = 0; m < MT; m++)
#pragma unroll
        for (int n = 0; n < NT; n++)
#pragma unroll
            for (int i = 0; i < 4; i++) acc[m][n][i] = 0.f;

    stage(0, 0);
    cp_commit();

    for (int g = 0; g < G; g++) {
        if (g + 1 < G) { stage(g + 1, (g + 1) & 1); cp_commit(); cp_wait1(); }
        else           { cp_wait0(); }
        __syncthreads();

        const uint32_t AH = sb0 + (g & 1) * BUF, AL = AH + 16384, BB = AL + 16384;

#pragma unroll
        for (int s = 0; s < 4; s++) {
            uint32_t a_h[MT][4], a_l[MT][4];
#pragma unroll
            for (int m = 0; m < MT; m++) {
                uint32_t row = (uint32_t)(wm * 32 + m * 16 + li + (g4 & 1) * 8);
                uint32_t kb = (uint32_t)(s * 32 + (g4 >> 1) * 16);
                uint32_t off = row * 128 + (kb ^ ((row & 7) << 4));
                ldsm4(a_h[m], AH + off);
                ldsm4(a_l[m], AL + off);
            }
            uint32_t bq[NT][4];
#pragma unroll
            for (int n = 0; n < NT; n++) {
                uint32_t nt = (uint32_t)(wn * NT + n);
                lds128(bq[n], BB + ((uint32_t)(s * 8 + nt) * 32 + lane) * 16);
            }
#pragma unroll
            for (int m = 0; m < MT; m++)
#pragma unroll
                for (int n = 0; n < NT; n++) {
                    mma16816(acc[m][n], a_h[m], bq[n]);
                    mma16816(acc[m][n], a_h[m], bq[n] + 2);
                    mma16816(acc[m][n], a_l[m], bq[n]);
                }
        }
        __syncthreads();
    }

#pragma unroll
    for (int m = 0; m < MT; m++) {
        int pr0 = p0 + wm * 32 + m * 16 + (lane >> 2);
#pragma unroll
        for (int n = 0; n < NT; n++) {
            int oc = (wn * NT + n) * 8 + (lane & 3) * 2;
            float bs0 = sbias[oc], bs1 = sbias[oc + 1];
#pragma unroll
            for (int half = 0; half < 2; half++) {
                int pr = pr0 + half * 8;
                float v0 = fmaxf(acc[m][n][half * 2 + 0] + bs0, 0.f);
                float v1 = fmaxf(acc[m][n][half * 2 + 1] + bs1, 0.f);
                uint32_t lo, hi = splitp(v0, v1, lo);
                size_t off = ((size_t)b * HH + pr) * 64 + oc;
                *(uint32_t*)(outh + off) = hi;
                *(uint32_t*)(outl + off) = lo;
            }
        }
    }
}

// ---------------- row-slab conv, CIN=64, H>=128: B resident across 4 tiles ------
#define CR_SMEM 215040
__global__ __launch_bounds__(256, 1) void convrow64_kernel(
    const bf* __restrict__ inh, const bf* __restrict__ inl,
    bf* __restrict__ outh, bf* __restrict__ outl,
    const float* __restrict__ wbuf, int wmoff, int boff, int H, int lgH)
{
    constexpr int TPC = 4;
    constexpr int NS = 3 * TPC;
    constexpr int ASZ = 33792;
    extern __shared__ __align__(128) char smem[];
    __shared__ float sbias[64];
    const int tid = threadIdx.x;
    const int b = blockIdx.z;
    const int p0base = blockIdx.x * (128 * TPC);
    const int HH = H * H;
    uint32_t sb0 = (uint32_t)__cvta_generic_to_shared(smem);
    const uint32_t BB = sb0;             // 147456 bytes, all 9 taps resident
    const uint32_t AB = sb0 + 147456;    // 2 * ASZ

    if (tid < 64) sbias[tid] = wbuf[(size_t)b * OUTD + boff + tid];

    const bf* ibh = inh + (size_t)b * HH * 64;
    const bf* ibl = inl + (size_t)b * HH * 64;
    const char* wcb = (const char*)(g_wmc + (size_t)b * WMTOT * 2 + (size_t)wmoff * 2);

    auto stageA = [&](int sj) {
        int tile = sj / 3, ky = sj - tile * 3;
        int p0t = p0base + tile * 128;
        int y = (p0t >> lgH) - 1 + ky;
        int x0t = p0t & (H - 1);
        bool rok = (unsigned)y < (unsigned)H;
        uint32_t Ab = AB + (uint32_t)(sj & 1) * ASZ;
        for (int idx = tid; idx < 1040; idx += 256) {
            int p = idx >> 3, jx = idx & 7;
            int x = x0t - 1 + p;
            bool ok = rok && ((unsigned)x < (unsigned)H);
            const char* sh = (const char*)ibh;
            const char* sl = (const char*)ibl;
            if (ok) {
                size_t q = ((size_t)y * H + x) * 64;
                sh = (const char*)(ibh + q) + jx * 16;
                sl = (const char*)(ibl + q) + jx * 16;
            }
            uint32_t o = (uint32_t)p * 128u + (((uint32_t)jx * 16u) ^ (((uint32_t)p & 7u) << 4));
            int sz = ok ? 16 : 0;
            cp16z(Ab + o, sh, sz);
            cp16z(Ab + 16896 + o, sl, sz);
        }
    };

    // stage all 9 B taps + slab 0 in group 0
    for (int idx = tid; idx < 9216; idx += 256) {
        int t = idx >> 10;
        uint32_t within = (uint32_t)(idx & 1023) * 16u;
        cp16(BB + (uint32_t)t * 16384u + within, wcb + (size_t)t * 16384 + within);
    }
    stageA(0);
    cp_commit();

    const int lane = tid & 31, w = tid >> 5;
    const int wm = w & 3, wn = w >> 2;   // 4 px-tiles x 2 oc-tiles
    const int g4 = lane >> 3, li = lane & 7;

    float acc[2][4][4];

    for (int sj = 0; sj < NS; sj++) {
        const int tile = sj / 3, ky = sj - tile * 3;
        if (sj + 1 < NS) { stageA(sj + 1); cp_commit(); cp_wait1(); }
        else             { cp_wait0(); }
        __syncthreads();

        if (ky == 0) {
#pragma unroll
            for (int m = 0; m < 2; m++)
#pragma unroll
                for (int n = 0; n < 4; n++)
#pragma unroll
                    for (int i = 0; i < 4; i++) acc[m][n][i] = 0.f;
        }

        uint32_t Ab = AB + (uint32_t)(sj & 1) * ASZ;
#pragma unroll
        for (int kx = 0; kx < 3; kx++) {
            uint32_t Bt = BB + (uint32_t)(ky * 3 + kx) * 16384u;
#pragma unroll
            for (int s = 0; s < 4; s++) {
                uint32_t a_h[2][4], a_l[2][4];
#pragma unroll
                for (int m = 0; m < 2; m++) {
                    uint32_t r = (uint32_t)(wm * 32 + m * 16 + li + (g4 & 1) * 8);
                    uint32_t si = r + (uint32_t)kx;
                    uint32_t off = si * 128 + (((uint32_t)(s * 32 + (g4 >> 1) * 16)) ^ ((si & 7) << 4));
                    ldsm4(a_h[m], Ab + off);
                    ldsm4(a_l[m], Ab + 16896 + off);
                }
                uint32_t bq[4][4];
#pragma unroll
                for (int n = 0; n < 4; n++)
                    lds128(bq[n], Bt + ((uint32_t)((s * 8 + wn * 4 + n) * 32 + lane)) * 16);
#pragma unroll
                for (int m = 0; m < 2; m++)
#pragma unroll
                    for (int n = 0; n < 4; n++) {
                        mma16816(acc[m][n], a_h[m], bq[n]);
                        mma16816(acc[m][n], a_h[m], bq[n] + 2);
                        mma16816(acc[m][n], a_l[m], bq[n]);
                    }
            }
        }

        if (ky == 2) {
            int p0t = p0base + tile * 128;
#pragma unroll
            for (int m = 0; m < 2; m++) {
                int pr0 = p0t + wm * 32 + m * 16 + (lane >> 2);
#pragma unroll
                for (int n = 0; n < 4; n++) {
                    int oc = (wn * 4 + n) * 8 + (lane & 3) * 2;
                    float bs0 = sbias[oc], bs1 = sbias[oc + 1];
#pragma unroll
                    for (int half = 0; half < 2; half++) {
                        int pr = pr0 + half * 8;
                        float v0 = fmaxf(acc[m][n][half * 2 + 0] + bs0, 0.f);
                        float v1 = fmaxf(acc[m][n][half * 2 + 1] + bs1, 0.f);
                        uint32_t lo, hi = splitp(v0, v1, lo);
                        size_t off = ((size_t)b * HH + pr) * 64 + oc;
                        *(uint32_t*)(outh + off) = hi;
                        *(uint32_t*)(outl + off) = lo;
                    }
                }
            }
        }
        __syncthreads();
    }
}

// ---------------- row-slab conv (CIN=128, H>=128): R15 path ----------------
__global__ __launch_bounds__(256, 1) void convrow128_kernel(
    const bf* __restrict__ inh, const bf* __restrict__ inl,
    bf* __restrict__ outh, bf* __restrict__ outl,
    const float* __restrict__ wbuf, int wmoff, int boff, int H, int lgH)
{
    constexpr int CIN = 128;
    constexpr int CBLK = 2;
    constexpr int ASZ = 33792;
    extern __shared__ __align__(128) char smem[];
    __shared__ float sbias[64];
    const int tid = threadIdx.x;
    const int b = blockIdx.z;
    const int p0 = blockIdx.x * 128;
    const int HH = H * H;
    uint32_t sb0 = (uint32_t)__cvta_generic_to_shared(smem);
    const uint32_t BB = sb0;
    const uint32_t AB = sb0 + 147456;

    if (tid < 64) sbias[tid] = wbuf[(size_t)b * OUTD + boff + tid];

    const bf* ibh = inh + (size_t)b * HH * CIN;
    const bf* ibl = inl + (size_t)b * HH * CIN;
    const char* wcb = (const char*)(g_wmc + (size_t)b * WMTOT * 2 + (size_t)wmoff * 2);

    const int y0 = p0 >> lgH;
    const int x0 = p0 & (H - 1);

    auto stageA = [&](int ky, int cb, int buf) {
        int y = y0 - 1 + ky;
        bool rok = (unsigned)y < (unsigned)H;
        uint32_t Ab = AB + (uint32_t)buf * ASZ;
        for (int idx = tid; idx < 1040; idx += 256) {
            int p = idx >> 3, jx = idx & 7;
            int x = x0 - 1 + p;
            bool ok = rok && ((unsigned)x < (unsigned)H);
            const char* sh = (const char*)ibh;
            const char* sl = (const char*)ibl;
            if (ok) {
                size_t q = ((size_t)y * H + x) * CIN + cb * 64;
                sh = (const char*)(ibh + q) + jx * 16;
                sl = (const char*)(ibl + q) + jx * 16;
            }
            uint32_t o = (uint32_t)p * 128u + (((uint32_t)jx * 16u) ^ (((uint32_t)p & 7u) << 4));
            int sz = ok ? 16 : 0;
            cp16z(Ab + o, sh, sz);
            cp16z(Ab + 16896 + o, sl, sz);
        }
    };
    auto stageB = [&](int ky, int cb) {
        for (int idx = tid; idx < 3072; idx += 256) {
            int tl = idx >> 10;
            uint32_t within = (uint32_t)(idx & 1023) * 16u;
            int t = ky * 3 + tl;
            int g = t * 2 + cb;
            cp16(BB + (uint32_t)t * 16384u + within, wcb + (size_t)g * 16384 + within);
        }
    };

    const int lane = tid & 31, w = tid >> 5;
    const int wm = w & 3, wn = w >> 2;
    const int g4 = lane >> 3, li = lane & 7;

    float acc[2][4][4];
#pragma unroll
    for (int m = 0; m < 2; m++)
#pragma unroll
        for (int n = 0; n < 4; n++)
#pragma unroll
            for (int i = 0; i < 4; i++) acc[m][n][i] = 0.f;

    for (int cb = 0; cb < CBLK; cb++) {
        stageA(0, cb, 0);
        stageB(0, cb);
        cp_commit();
        for (int ky = 0; ky < 3; ky++) {
            if (ky < 2) { stageA(ky + 1, cb, (ky + 1) & 1); stageB(ky + 1, cb); cp_commit(); cp_wait1(); }
            else        { cp_wait0(); }
            __syncthreads();
            uint32_t Ab = AB + (uint32_t)(ky & 1) * ASZ;
#pragma unroll
            for (int kx = 0; kx < 3; kx++) {
                uint32_t Bt = BB + (uint32_t)(ky * 3 + kx) * 16384u;
#pragma unroll
                for (int s = 0; s < 4; s++) {
                    uint32_t a_h[2][4], a_l[2][4];
#pragma unroll
                    for (int m = 0; m < 2; m++) {
                        uint32_t r = (uint32_t)(wm * 32 + m * 16 + li + (g4 & 1) * 8);
                        uint32_t si = r + (uint32_t)kx;
                        uint32_t off = si * 128 + (((uint32_t)(s * 32 + (g4 >> 1) * 16)) ^ ((si & 7) << 4));
                        ldsm4(a_h[m], Ab + off);
                        ldsm4(a_l[m], Ab + 16896 + off);
                    }
                    uint32_t bq[4][4];
#pragma unroll
                    for (int n = 0; n < 4; n++)
                        lds128(bq[n], Bt + ((uint32_t)((s * 8 + wn * 4 + n) * 32 + lane)) * 16);
#pragma unroll
                    for (int m = 0; m < 2; m++)
#pragma unroll
                        for (int n = 0; n < 4; n++) {
                            mma16816(acc[m][n], a_h[m], bq[n]);
                            mma16816(acc[m][n], a_h[m], bq[n] + 2);
                            mma16816(acc[m][n], a_l[m], bq[n]);
                        }
                }
            }
            __syncthreads();
        }
    }

#pragma unroll
    for (int m = 0; m < 2; m++) {
        int pr0 = p0 + wm * 32 + m * 16 + (lane >> 2);
#pragma unroll
        for (int n = 0; n < 4; n++) {
            int oc = (wn * 4 + n) * 8 + (lane & 3) * 2;
            float bs0 = sbias[oc], bs1 = sbias[oc + 1];
#pragma unroll
            for (int half = 0; half < 2; half++) {
                int pr = pr0 + half * 8;
                float v0 = fmaxf(acc[m][n][half * 2 + 0] + bs0, 0.f);
                float v1 = fmaxf(acc[m][n][half * 2 + 1] + bs1, 0.f);
                uint32_t lo, hi = splitp(v0, v1, lo);
                size_t off = ((size_t)b * HH + pr) * 64 + oc;
                *(uint32_t*)(outh + off) = hi;
                *(uint32_t*)(outl + off) = lo;
            }
        }
    }
}

// ---------------- 2x2 maxpool (NHWC hi/lo) ----------------
__global__ void maxpool_bf(const bf* __restrict__ ih, const bf* __restrict__ il,
                           bf* __restrict__ oh, bf* __restrict__ ol, int H)
{
    int Wo = H >> 1;
    int total = B * Wo * Wo * 64;
    int idx = blockIdx.x * 256 + threadIdx.x;
    if (idx >= total) return;
    int c = idx & 63, t = idx >> 6;
    int xo = t % Wo; t /= Wo;
    int yo = t % Wo; int b = t / Wo;
    size_t base = (((size_t)b * H + 2 * yo) * H + 2 * xo) * 64 + c;
    size_t rs = (size_t)H * 64;
    float v = fmaxf(fmaxf(joinv(ih[base], il[base]), joinv(ih[base + 64], il[base + 64])),
                    fmaxf(joinv(ih[base + rs], il[base + rs]), joinv(ih[base + rs + 64], il[base + rs + 64])));
    bf h = __float2bfloat16(v);
    oh[idx] = h;
    ol[idx] = __float2bfloat16(v - __bfloat162float(h));
}

// ---------------- bilinear x2 upsample + concat ----------------
__global__ void upconcat_bf(const bf* __restrict__ ih, const bf* __restrict__ il,
                            const bf* __restrict__ skh, const bf* __restrict__ skl,
                            bf* __restrict__ oh, bf* __restrict__ ol, int H)
{
    int Ho = H * 2;
    int total = B * Ho * Ho * 128;
    int idx = blockIdx.x * 256 + threadIdx.x;
    if (idx >= total) return;
    int c = idx & 127, t = idx >> 7;
    int xo = t % Ho; t /= Ho;
    int yo = t % Ho; int b = t / Ho;
    if (c >= 64) {
        size_t s = (((size_t)b * Ho + yo) * Ho + xo) * 64 + (c - 64);
        oh[idx] = skh[s];
        ol[idx] = skl[s];
        return;
    }
    float ys = (float)yo * (float)(H - 1) / (float)(Ho - 1);
    float xs = (float)xo * (float)(H - 1) / (float)(Ho - 1);
    int y0 = (int)floorf(ys); int y1 = min(y0 + 1, H - 1);
    int x0 = (int)floorf(xs); int x1 = min(x0 + 1, H - 1);
    float wy = ys - (float)y0, wx = xs - (float)x0;
    const bf* ph = ih + (size_t)b * H * H * 64 + c;
    const bf* pl = il + (size_t)b * H * H * 64 + c;
#define AT(y, x) joinv(ph[((size_t)(y) * H + (x)) * 64], pl[((size_t)(y) * H + (x)) * 64])
    float r0 = AT(y0, x0) * (1.f - wy) + AT(y1, x0) * wy;
    float r1 = AT(y0, x1) * (1.f - wy) + AT(y1, x1) * wy;
#undef AT
    float v = r0 * (1.f - wx) + r1 * wx;
    bf h = __float2bfloat16(v);
    oh[idx] = h;
    ol[idx] = __float2bfloat16(v - __bfloat162float(h));
}

// ---------------- final 1x1 conv (64->2) + residual, NHWC ----------------
__global__ void final_bf(const bf* __restrict__ ih, const bf* __restrict__ il,
                         const float* __restrict__ zf, const float* __restrict__ wbuf,
                         float* __restrict__ out)
{
    __shared__ float sw[130];
    int b = blockIdx.y, tid = threadIdx.x;
    const float* wb = wbuf + (size_t)b * OUTD;
    if (tid < 128) sw[tid] = wb[590976 + tid];
    else if (tid < 130) sw[tid] = wb[592000 + (tid - 128)];
    __syncthreads();
    int hw = blockIdx.x * 256 + tid;
    const bf* ph = ih + ((size_t)b * 65536 + hw) * 64;
    const bf* pl = il + ((size_t)b * 65536 + hw) * 64;
    float a0 = sw[128], a1 = sw[129];
#pragma unroll 16
    for (int c = 0; c < 64; c++) {
        float v = joinv(ph[c], pl[c]);
        a0 = fmaf(v, sw[c], a0);
        a1 = fmaf(v, sw[64 + c], a1);
    }
    size_t o = ((size_t)b * 65536 + hw) * 2;
    out[o] = zf[o] + a0;
    out[o + 1] = zf[o + 1] + a1;
}

// ---------------- host ----------------
static const int WMh[13] = {0, 36864, 73728, 110592, 147456, 184320, 221184, 258048,
                            331776, 368640, 442368, 479232, 552960};
static const int CINh[13] = {64, 64, 64, 64, 64, 64, 64, 128, 64, 128, 64, 128, 64};

static inline void launch_mm(const bf* ih, const bf* il, bf* oh, bf* ol,
                             const float* pw, int layer, int H, int lgH)
{
    int wmoff = WMh[layer - 1];
    int boff = 591104 + 64 * layer;
    int cin = CINh[layer - 1];
    if (H >= 128) {
        if (cin == 64) {
            dim3 gs((H * H) / 512, 1, B);
            convrow64_kernel<<<gs, 256, CR_SMEM>>>(ih, il, oh, ol, pw, wmoff, boff, H, lgH);
        } else {
            dim3 gs((H * H) / 128, 1, B);
            convrow128_kernel<<<gs, 256, CR_SMEM>>>(ih, il, oh, ol, pw, wmoff, boff, H, lgH);
        }
    } else {
        dim3 gs((H * H) / 128, 1, B);
        if (cin == 64)
            convmm_kernel<64><<<gs, 256, CMM_SMEM>>>(ih, il, oh, ol, pw, wmoff, boff, H, lgH);
        else
            convmm_kernel<128><<<gs, 256, CMM_SMEM>>>(ih, il, oh, ol, pw, wmoff, boff, H, lgH);
    }
}

extern "C" void kernel_launch(void* const* d_in, const int* in_sizes, int n_in,
                              void* d_out, int out_size)
{
    const float* zf = (const float*)d_in[0];
    const float* hp = (const float*)d_in[2];
    const float* W1 = (const float*)d_in[3];
    const float* b1 = (const float*)d_in[4];
    const float* W2 = (const float*)d_in[5];
    const float* b2 = (const float*)d_in[6];
    const float* Wo = (const float*)d_in[7];
    const float* bo = (const float*)d_in[8];
    float* out = (float*)d_out;
    float* l1 = out + (size_t)B * 131072;

    cudaFuncSetAttribute(convmm_kernel<64>, cudaFuncAttributeMaxDynamicSharedMemorySize, CMM_SMEM);
    cudaFuncSetAttribute(convmm_kernel<128>, cudaFuncAttributeMaxDynamicSharedMemorySize, CMM_SMEM);
    cudaFuncSetAttribute(convrow64_kernel, cudaFuncAttributeMaxDynamicSharedMemorySize, CR_SMEM);
    cudaFuncSetAttribute(convrow128_kernel, cudaFuncAttributeMaxDynamicSharedMemorySize, CR_SMEM);

    float* pW;
    bf *Ah, *Al, *Bh, *Bl, *S1h, *S1l, *S2h, *S2l, *S3h, *S3l;
    cudaGetSymbolAddress((void**)&pW, g_w);
    cudaGetSymbolAddress((void**)&Ah, g_Ah);
    cudaGetSymbolAddress((void**)&Al, g_Al);
    cudaGetSymbolAddress((void**)&Bh, g_Bh);
    cudaGetSymbolAddress((void**)&Bl, g_Bl);
    cudaGetSymbolAddress((void**)&S1h, g_S1h);
    cudaGetSymbolAddress((void**)&S1l, g_S1l);
    cudaGetSymbolAddress((void**)&S2h, g_S2h);
    cudaGetSymbolAddress((void**)&S2l, g_S2l);
    cudaGetSymbolAddress((void**)&S3h, g_S3h);
    cudaGetSymbolAddress((void**)&S3l, g_S3l);

    hyper1_kernel<<<1, 256>>>(hp, W1, b1, W2, b2, l1);
    weightgen_kernel<<<(OUTD + 255) / 256, 256>>>(Wo, bo, l1);
    repack0_kernel<<<(B * 576 + 255) / 256, 256>>>();

    // encoder
    conv0_kernel<<<dim3(64, 4, B), 256>>>(zf, Ah, Al, pW);
    launch_mm(Ah, Al, S1h, S1l, pW, 1, 256, 8);
    { int n = B * 128 * 128 * 64; maxpool_bf<<<(n + 255) / 256, 256>>>(S1h, S1l, Bh, Bl, 256); }
    launch_mm(Bh, Bl, Ah, Al, pW, 2, 128, 7);
    launch_mm(Ah, Al, S2h, S2l, pW, 3, 128, 7);
    { int n = B * 64 * 64 * 64; maxpool_bf<<<(n + 255) / 256, 256>>>(S2h, S2l, Bh, Bl, 128); }
    launch_mm(Bh, Bl, Ah, Al, pW, 4, 64, 6);
    launch_mm(Ah, Al, S3h, S3l, pW, 5, 64, 6);
    { int n = B * 32 * 32 * 64; maxpool_bf<<<(n + 255) / 256, 256>>>(S3h, S3l, Bh, Bl, 64); }
    launch_mm(Bh, Bl, Ah, Al, pW, 6, 32, 5);
    launch_mm(Ah, Al, Bh, Bl, pW, 7, 32, 5);

    // decoder
    { int n = B * 64 * 64 * 128; upconcat_bf<<<(n + 255) / 256, 256>>>(Bh, Bl, S3h, S3l, Ah, Al, 32); }
    launch_mm(Ah, Al, Bh, Bl, pW, 8, 64, 6);
    launch_mm(Bh, Bl, Ah, Al, pW, 9, 64, 6);
    { int n = B * 128 * 128 * 128; upconcat_bf<<<(n + 255) / 256, 256>>>(Ah, Al, S2h, S2l, Bh, Bl, 64); }
    launch_mm(Bh, Bl, Ah, Al, pW, 10, 128, 7);
    launch_mm(Ah, Al, Bh, Bl, pW, 11, 128, 7);
    { int n = B * 256 * 256 * 128; upconcat_bf<<<(n + 255) / 256, 256>>>(Bh, Bl, S1h, S1l, Ah, Al, 128); }
    launch_mm(Ah, Al, Bh, Bl, pW, 12, 256, 8);
    launch_mm(Bh, Bl, Ah, Al, pW, 13, 256, 8);

    final_bf<<<dim3(256, B), 256>>>(Ah, Al, zf, pW, out);
}